// round 11
// baseline (speedup 1.0000x reference)
#include <cuda_runtime.h>
#include <cuda_bf16.h>
#include <cstdint>

#define B_ 2
#define N_ 2048
#define DIM_ 1024
#define H_ 16
#define DH_ 64
#define INNER_ 1024
// SCALE * log2(e): softmax computed in base-2 domain
#define QSCALE_ (0.125f * 1.4426950408889634f)
#define KFULL_ 3072          // B-side split K = 3 * 1024
#define KA_ 2048             // A-side split K = 2 * 1024 (term 3 reuses hi)
#define NITER_ 96            // KFULL / 32

// ---------------------------------------------------------------------------
// Scratch (device globals: no cudaMalloc allowed)
// ---------------------------------------------------------------------------
__device__ float g_qkv[B_ * N_ * 3 * INNER_];   // [B,N,3*INNER]
__device__ float g_att[B_ * N_ * INNER_];       // [B,N,INNER]

// attention operands, pre-split bf16
__device__ __nv_bfloat16 g_qs[32 * N_ * 128];   // [bh][n][qh|ql] (scaled, log2e folded)
__device__ __nv_bfloat16 g_ks[32 * N_ * 192];   // [bh][n][kh|kh|kl]
__device__ __nv_bfloat16 g_vh[32 * N_ * 64];
__device__ __nv_bfloat16 g_vl[32 * N_ * 64];

// bf16 split buffers for projection GEMMs
__device__ __nv_bfloat16 g_ax[4096 * KA_];      // activations [hi|lo]
__device__ __nv_bfloat16 g_bq[3072 * KFULL_];   // w_qkv split [hi|hi|lo]
__device__ __nv_bfloat16 g_bo[1024 * KFULL_];   // w_out split [hi|hi|lo]

// ---------------------------------------------------------------------------
// PTX helpers (arch-portable: compile under compute_103)
// ---------------------------------------------------------------------------
__device__ __forceinline__ uint32_t smem_to_u32(const void* p) {
    uint32_t a;
    asm("{ .reg .u64 t; cvta.to.shared.u64 t, %1; cvt.u32.u64 %0, t; }" : "=r"(a) : "l"(p));
    return a;
}
__device__ __forceinline__ void cp_async16(uint32_t dst, const void* src) {
    asm volatile("cp.async.cg.shared.global [%0], [%1], 16;\n" :: "r"(dst), "l"(src));
}
#define CP_COMMIT()  asm volatile("cp.async.commit_group;\n" ::: "memory")
#define CP_WAIT2()   asm volatile("cp.async.wait_group 2;\n" ::: "memory")
#define CP_WAIT1()   asm volatile("cp.async.wait_group 1;\n" ::: "memory")
#define CP_WAIT0()   asm volatile("cp.async.wait_group 0;\n" ::: "memory")

#define LDMATRIX_X4(r, addr) \
    asm volatile("ldmatrix.sync.aligned.m8n8.x4.shared.b16 {%0,%1,%2,%3}, [%4];" \
        : "=r"((r)[0]), "=r"((r)[1]), "=r"((r)[2]), "=r"((r)[3]) : "r"(addr))

#define LDMATRIX_X4_T(r, addr) \
    asm volatile("ldmatrix.sync.aligned.m8n8.x4.trans.shared.b16 {%0,%1,%2,%3}, [%4];" \
        : "=r"((r)[0]), "=r"((r)[1]), "=r"((r)[2]), "=r"((r)[3]) : "r"(addr))

#define MMA16816(c, a, b0, b1) \
    asm volatile("mma.sync.aligned.m16n8k16.row.col.f32.bf16.bf16.f32 " \
        "{%0,%1,%2,%3}, {%4,%5,%6,%7}, {%8,%9}, {%0,%1,%2,%3};" \
        : "+f"((c)[0]), "+f"((c)[1]), "+f"((c)[2]), "+f"((c)[3]) \
        : "r"((a)[0]), "r"((a)[1]), "r"((a)[2]), "r"((a)[3]), "r"(b0), "r"(b1))

// pack bf16x2 from two fp32 (lo -> low half, hi -> high half), round-nearest
#define PACK_BF16X2_RN(d, lo, hi) \
    asm("cvt.rn.bf16x2.f32 %0, %1, %2;" : "=r"(d) : "f"(hi), "f"(lo))

// ---------------------------------------------------------------------------
// fp32 -> bf16 split conversion.
// modeB=1 (weights): 3-term rows [hi | hi | lo], stride KFULL_ (3072)
// modeB=0 (activations): 2-term rows [hi | lo], stride KA_ (2048)
// Term pairing in GEMM: (Ah,Bh), (Al,Bh), (Ah,Bl) — residual ~2^-16.
// ---------------------------------------------------------------------------
__global__ void split_kernel(const float* __restrict__ src, __nv_bfloat16* __restrict__ dst,
                             int total_quads, int modeB)
{
    int i = blockIdx.x * blockDim.x + threadIdx.x;
    if (i >= total_quads) return;
    int r = i >> 8;              // / 256  (K=1024 -> 256 quads per row)
    int c = (i & 255) << 2;
    float4 v = ((const float4*)src)[i];

    __nv_bfloat16 h0 = __float2bfloat16_rn(v.x), h1 = __float2bfloat16_rn(v.y);
    __nv_bfloat16 h2 = __float2bfloat16_rn(v.z), h3 = __float2bfloat16_rn(v.w);
    __nv_bfloat16 l0 = __float2bfloat16_rn(v.x - __bfloat162float(h0));
    __nv_bfloat16 l1 = __float2bfloat16_rn(v.y - __bfloat162float(h1));
    __nv_bfloat16 l2 = __float2bfloat16_rn(v.z - __bfloat162float(h2));
    __nv_bfloat16 l3 = __float2bfloat16_rn(v.w - __bfloat162float(h3));

    __nv_bfloat162 hA = __nv_bfloat162(h0, h1), hB = __nv_bfloat162(h2, h3);
    __nv_bfloat162 lA = __nv_bfloat162(l0, l1), lB = __nv_bfloat162(l2, l3);

    if (modeB) {
        size_t base = (size_t)r * KFULL_ + c;
        __nv_bfloat162* d0 = (__nv_bfloat162*)(dst + base);
        __nv_bfloat162* d1 = (__nv_bfloat162*)(dst + base + 1024);
        __nv_bfloat162* d2 = (__nv_bfloat162*)(dst + base + 2048);
        d0[0] = hA; d0[1] = hB;
        d1[0] = hA; d1[1] = hB;
        d2[0] = lA; d2[1] = lB;
    } else {
        size_t base = (size_t)r * KA_ + c;
        __nv_bfloat162* d0 = (__nv_bfloat162*)(dst + base);
        __nv_bfloat162* d1 = (__nv_bfloat162*)(dst + base + 1024);
        d0[0] = hA; d0[1] = hB;
        d1[0] = lA; d1[1] = lB;
    }
}

// ---------------------------------------------------------------------------
// mma.sync bf16 NT GEMM: C[m,n] = sum_k A[m,k']*B[n,k] (+bias)
// A: [M, 2048] (k' = k mod 2048: term 3 reuses A-hi), B: [Ncol, 3072].
// CTA tile 128x128, BK=32, 8 warps (64x32), 4-stage cp.async pipeline.
// ---------------------------------------------------------------------------
#define BK_ 32
#define ROWB_ 80
#define STAGE_ (128 * ROWB_ * 2)
#define GEMM_SMEM (4 * STAGE_)

__global__ __launch_bounds__(256, 2) void gemm_mma(
    const __nv_bfloat16* __restrict__ A, const __nv_bfloat16* __restrict__ Bm,
    float* __restrict__ C, const float* __restrict__ bias, int Ncol)
{
    extern __shared__ char smem_raw[];
    const uint32_t sb = smem_to_u32(smem_raw);

    const int tid = threadIdx.x;
    const int lane = tid & 31, wid = tid >> 5;
    const int bm = blockIdx.y * 128, bn = blockIdx.x * 128;
    const int wm = (wid >> 2) * 64, wn = (wid & 3) * 32;

    const __nv_bfloat16* Abase = A + (size_t)bm * KA_;
    const __nv_bfloat16* Bbase = Bm + (size_t)bn * KFULL_;

    const int lrow = tid >> 1;
    const int lhalfB = (tid & 1) * 32;
    const int lhalfE = (tid & 1) * 16;
    const uint32_t so = (uint32_t)(lrow * ROWB_ + lhalfB);

    const uint32_t a_off = (uint32_t)((wm + (lane & 15)) * ROWB_ + (lane >> 4) * 16);
    const uint32_t b_off = (uint32_t)((wn + ((lane >> 4) << 3) + (lane & 7)) * ROWB_
                                      + ((lane >> 3) & 1) * 16);

    float acc[4][4][4];
#pragma unroll
    for (int mi = 0; mi < 4; mi++)
#pragma unroll
        for (int ni = 0; ni < 4; ni++)
#pragma unroll
            for (int r = 0; r < 4; r++) acc[mi][ni][r] = 0.f;

    auto load_tile = [&](int it) {
        uint32_t sa = sb + (uint32_t)(it & 3) * STAGE_;
        uint32_t sbb = sa + 128 * ROWB_;
        int kA = (it & 63) * BK_;          // A k wraps at 2048
        const __nv_bfloat16* Ag = Abase + (size_t)lrow * KA_ + kA + lhalfE;
        const __nv_bfloat16* Bg = Bbase + (size_t)lrow * KFULL_ + it * BK_ + lhalfE;
        cp_async16(sa + so, Ag);
        cp_async16(sa + so + 16, Ag + 8);
        cp_async16(sbb + so, Bg);
        cp_async16(sbb + so + 16, Bg + 8);
        CP_COMMIT();
    };

    load_tile(0);
    load_tile(1);
    load_tile(2);

    for (int it = 0; it < NITER_; it++) {
        CP_WAIT2();
        __syncthreads();
        if (it + 3 < NITER_) load_tile(it + 3);

        uint32_t sa = sb + (uint32_t)(it & 3) * STAGE_;
        uint32_t sbb = sa + 128 * ROWB_;
#pragma unroll
        for (int ks = 0; ks < 2; ks++) {
            uint32_t af[4][4], bf[2][4];
#pragma unroll
            for (int mi = 0; mi < 4; mi++)
                LDMATRIX_X4(af[mi], sa + a_off + mi * (16 * ROWB_) + ks * 32);
#pragma unroll
            for (int nb = 0; nb < 2; nb++)
                LDMATRIX_X4(bf[nb], sbb + b_off + nb * (16 * ROWB_) + ks * 32);
#pragma unroll
            for (int mi = 0; mi < 4; mi++)
#pragma unroll
                for (int ni = 0; ni < 4; ni++)
                    MMA16816(acc[mi][ni], af[mi], bf[ni >> 1][(ni & 1) * 2],
                             bf[ni >> 1][(ni & 1) * 2 + 1]);
        }
    }

#pragma unroll
    for (int mi = 0; mi < 4; mi++) {
        int row = bm + wm + mi * 16 + (lane >> 2);
#pragma unroll
        for (int ni = 0; ni < 4; ni++) {
            int col = bn + wn + ni * 8 + (lane & 3) * 2;
            float b0 = 0.f, b1 = 0.f;
            if (bias) { b0 = bias[col]; b1 = bias[col + 1]; }
            float2 v0 = make_float2(acc[mi][ni][0] + b0, acc[mi][ni][1] + b1);
            float2 v1 = make_float2(acc[mi][ni][2] + b0, acc[mi][ni][3] + b1);
            *(float2*)(C + (size_t)row * Ncol + col) = v0;
            *(float2*)(C + (size_t)(row + 8) * Ncol + col) = v1;
        }
    }
}

// ---------------------------------------------------------------------------
// RoPE + split: g_qkv -> g_qs [qh|ql] (x QSCALE, log2e folded),
//               g_ks [kh|kh|kl], g_vh, g_vl
// ---------------------------------------------------------------------------
__device__ __forceinline__ void split2(float x, __nv_bfloat16& hi, __nv_bfloat16& lo) {
    hi = __float2bfloat16_rn(x);
    lo = __float2bfloat16_rn(x - __bfloat162float(hi));
}

__global__ void rope_split_kernel(const float* __restrict__ rot)
{
    int idx = blockIdx.x * blockDim.x + threadIdx.x;  // 32*2048*32 threads
    int d = idx & 31;
    int n = (idx >> 5) & (N_ - 1);
    int bh = idx >> 16;
    int b = bh >> 4, h = bh & 15;

    const float* base = g_qkv + ((size_t)(b * N_ + n)) * (3 * INNER_) + h * DH_ + d;
    float p1 = rot[n * DH_ + d];
    float p2 = rot[n * DH_ + d + 32];
    float c1 = cosf(p1), s1 = sinf(p1);
    float c2 = cosf(p2), s2 = sinf(p2);

    float q1 = base[0], q2 = base[32];
    float k1 = base[INNER_], k2 = base[INNER_ + 32];
    float v1 = base[2 * INNER_], v2 = base[2 * INNER_ + 32];

    float qr1 = (q1 * c1 - q2 * s1) * QSCALE_;
    float qr2 = (q2 * c2 + q1 * s2) * QSCALE_;
    float kr1 = k1 * c1 - k2 * s1;
    float kr2 = k2 * c2 + k1 * s2;

    __nv_bfloat16 qh1, ql1, qh2, ql2, kh1, kl1, kh2, kl2, vh1, vl1, vh2, vl2;
    split2(qr1, qh1, ql1); split2(qr2, qh2, ql2);
    split2(kr1, kh1, kl1); split2(kr2, kh2, kl2);
    split2(v1, vh1, vl1);  split2(v2, vh2, vl2);

    size_t qb = ((size_t)bh * N_ + n) * 128 + d;
    g_qs[qb]      = qh1; g_qs[qb + 32] = qh2;
    g_qs[qb + 64] = ql1; g_qs[qb + 96] = ql2;

    size_t kb = ((size_t)bh * N_ + n) * 192 + d;
    g_ks[kb]       = kh1; g_ks[kb + 32]  = kh2;
    g_ks[kb + 64]  = kh1; g_ks[kb + 96]  = kh2;
    g_ks[kb + 128] = kl1; g_ks[kb + 160] = kl2;

    size_t vb = ((size_t)bh * N_ + n) * 64 + d;
    g_vh[vb] = vh1; g_vh[vb + 32] = vh2;
    g_vl[vb] = vl1; g_vl[vb + 32] = vl2;
}

// ---------------------------------------------------------------------------
// Tensor-core flash attention.
// CTA: 128 q-rows (8 warps x 16), key tiles of 64, double-buffered cp.async.
// Q frags register-resident via direct LDG (mma A-frag layout); the 3rd
// S-term reuses the qh frags (af[8] covers K=192). Softmax in base-2.
// O += Ph*Vh + Pl*Vh + Ph*Vl (P split in registers). Occupancy 2 CTAs/SM.
// ---------------------------------------------------------------------------
#define KT_ 64                   // keys per tile
#define NT_ (N_ / KT_)           // 32 tiles
#define KROWB_ 400               // 192 bf16 + 8 pad = 200 el
#define VROWB_ 144               // 64 bf16 + 8 pad = 72 el
#define AST_BYTES (KT_ * KROWB_ + 2 * KT_ * VROWB_)  // 25600+18432 = 44032
#define ATTN_SMEM (2 * AST_BYTES)                    // 88064

__global__ __launch_bounds__(256, 2) void attn_mma()
{
    extern __shared__ char smem_raw[];
    const uint32_t sb = smem_to_u32(smem_raw);

    const int tid = threadIdx.x;
    const int lane = tid & 31, wid = tid >> 5;
    const int qt = blockIdx.x;       // q tile (16)
    const int bh = blockIdx.y;       // 32
    const int b = bh >> 4, h = bh & 15;

    const __nv_bfloat16* Kg = g_ks + (size_t)bh * N_ * 192;
    const __nv_bfloat16* Vhg = g_vh + (size_t)bh * N_ * 64;
    const __nv_bfloat16* Vlg = g_vl + (size_t)bh * N_ * 64;

    auto load_tile = [&](int t) {
        uint32_t st = sb + (uint32_t)(t & 1) * AST_BYTES;
        uint32_t vh_st = st + KT_ * KROWB_;
        uint32_t vl_st = vh_st + KT_ * VROWB_;
        int kb = t * KT_;
#pragma unroll
        for (int j = 0; j < 6; j++) {
            int idx = tid + j * 256;      // 1536 chunks
            int row = idx / 24, c = idx % 24;
            cp_async16(st + row * KROWB_ + c * 16, Kg + (size_t)(kb + row) * 192 + c * 8);
        }
#pragma unroll
        for (int j = 0; j < 2; j++) {
            int idx = tid + j * 256;      // 512 chunks
            int row = idx >> 3, c = idx & 7;
            cp_async16(vh_st + row * VROWB_ + c * 16, Vhg + (size_t)(kb + row) * 64 + c * 8);
            cp_async16(vl_st + row * VROWB_ + c * 16, Vlg + (size_t)(kb + row) * 64 + c * 8);
        }
        CP_COMMIT();
    };

    load_tile(0);

    // ---- Q fragments via direct LDG in mma A-frag layout ----
    // a0=(g, 2t), a1=(g+8, 2t), a2=(g, 2t+8), a3=(g+8, 2t+8); g=lane>>2, t=lane&3
    uint32_t af[8][4];
    {
        const __nv_bfloat16* q0 = g_qs
            + ((size_t)bh * N_ + qt * 128 + wid * 16 + (lane >> 2)) * 128 + (lane & 3) * 2;
        const __nv_bfloat16* q8 = q0 + 8 * 128;
#pragma unroll
        for (int ks = 0; ks < 8; ks++) {
            af[ks][0] = *(const uint32_t*)(q0 + ks * 16);
            af[ks][1] = *(const uint32_t*)(q8 + ks * 16);
            af[ks][2] = *(const uint32_t*)(q0 + ks * 16 + 8);
            af[ks][3] = *(const uint32_t*)(q8 + ks * 16 + 8);
        }
    }

    float O[8][4];
#pragma unroll
    for (int g = 0; g < 8; g++)
#pragma unroll
        for (int r = 0; r < 4; r++) O[g][r] = 0.f;
    float m0 = -1e30f, m1 = -1e30f, l0 = 0.f, l1 = 0.f;

    const uint32_t kb_off = (uint32_t)((((lane >> 4) << 3) + (lane & 7)) * KROWB_
                                       + ((lane >> 3) & 1) * 16);
    const uint32_t v_off = (uint32_t)((((lane >> 3) & 1) * 8 + (lane & 7)) * VROWB_
                                      + ((lane >> 4) << 3) * 2);

    for (int t = 0; t < NT_; t++) {
        if (t + 1 < NT_) { load_tile(t + 1); CP_WAIT1(); } else { CP_WAIT0(); }
        __syncthreads();

        uint32_t st = sb + (uint32_t)(t & 1) * AST_BYTES;
        uint32_t vh_st = st + KT_ * KROWB_;
        uint32_t vl_st = vh_st + KT_ * VROWB_;

        // ---- S = Q'K'^T : 8 key-blocks x 12 k-steps (af reused for ks>=8) ----
        float S[8][4];
#pragma unroll
        for (int g = 0; g < 8; g++)
#pragma unroll
            for (int r = 0; r < 4; r++) S[g][r] = 0.f;

#pragma unroll
        for (int ks = 0; ks < 12; ks++) {
            const uint32_t* aq = af[ks < 8 ? ks : ks - 8];
            uint32_t kf[4][4];
#pragma unroll
            for (int g = 0; g < 4; g++)
                LDMATRIX_X4(kf[g], st + kb_off + g * (16 * KROWB_) + ks * 32);
#pragma unroll
            for (int g = 0; g < 4; g++) {
                MMA16816(S[2 * g],     aq, kf[g][0], kf[g][1]);
                MMA16816(S[2 * g + 1], aq, kf[g][2], kf[g][3]);
            }
        }

        // ---- online softmax (base-2 domain) ----
        float mx0 = -1e30f, mx1 = -1e30f;
#pragma unroll
        for (int g = 0; g < 8; g++) {
            mx0 = fmaxf(mx0, fmaxf(S[g][0], S[g][1]));
            mx1 = fmaxf(mx1, fmaxf(S[g][2], S[g][3]));
        }
        mx0 = fmaxf(mx0, __shfl_xor_sync(0xffffffffu, mx0, 1));
        mx0 = fmaxf(mx0, __shfl_xor_sync(0xffffffffu, mx0, 2));
        mx1 = fmaxf(mx1, __shfl_xor_sync(0xffffffffu, mx1, 1));
        mx1 = fmaxf(mx1, __shfl_xor_sync(0xffffffffu, mx1, 2));

        float m0n = fmaxf(m0, mx0), m1n = fmaxf(m1, mx1);
        float corr0 = exp2f(m0 - m0n), corr1 = exp2f(m1 - m1n);
        m0 = m0n; m1 = m1n;
        l0 *= corr0; l1 *= corr1;

#pragma unroll
        for (int g = 0; g < 8; g++) {
            S[g][0] = exp2f(S[g][0] - m0);
            S[g][1] = exp2f(S[g][1] - m0);
            S[g][2] = exp2f(S[g][2] - m1);
            S[g][3] = exp2f(S[g][3] - m1);
            l0 += S[g][0] + S[g][1];
            l1 += S[g][2] + S[g][3];
            O[g][0] *= corr0; O[g][1] *= corr0;
            O[g][2] *= corr1; O[g][3] *= corr1;
        }

        // ---- O += P * V (3-term split) : 4 k-steps over keys ----
#pragma unroll
        for (int ks = 0; ks < 4; ks++) {
            uint32_t ph[4], pl[4];
#pragma unroll
            for (int half = 0; half < 2; half++) {
                const float* Sp = S[2 * ks + half];
#pragma unroll
                for (int pr = 0; pr < 2; pr++) {
                    float pa = Sp[2 * pr], pb = Sp[2 * pr + 1];
                    uint32_t ua = __float_as_uint(pa), ub = __float_as_uint(pb);
                    ph[2 * half + pr] = __byte_perm(ua, ub, 0x7632);
                    float ra = pa - __uint_as_float(ua & 0xffff0000u);
                    float rb = pb - __uint_as_float(ub & 0xffff0000u);
                    PACK_BF16X2_RN(pl[2 * half + pr], ra, rb);
                }
            }
#pragma unroll
            for (int g = 0; g < 4; g++) {
                uint32_t vh[4], vl[4];
                LDMATRIX_X4_T(vh, vh_st + v_off + ks * (16 * VROWB_) + g * 32);
                LDMATRIX_X4_T(vl, vl_st + v_off + ks * (16 * VROWB_) + g * 32);
                MMA16816(O[2 * g],     ph, vh[0], vh[1]);
                MMA16816(O[2 * g + 1], ph, vh[2], vh[3]);
                MMA16816(O[2 * g],     pl, vh[0], vh[1]);
                MMA16816(O[2 * g + 1], pl, vh[2], vh[3]);
                MMA16816(O[2 * g],     ph, vl[0], vl[1]);
                MMA16816(O[2 * g + 1], ph, vl[2], vl[3]);
            }
        }
        __syncthreads();
    }

    // ---- finalize ----
    l0 += __shfl_xor_sync(0xffffffffu, l0, 1);
    l0 += __shfl_xor_sync(0xffffffffu, l0, 2);
    l1 += __shfl_xor_sync(0xffffffffu, l1, 1);
    l1 += __shfl_xor_sync(0xffffffffu, l1, 2);
    float inv0 = 1.f / l0, inv1 = 1.f / l1;

    int row = qt * 128 + wid * 16 + (lane >> 2);
    float* ob = g_att + ((size_t)b * N_ + row) * INNER_ + h * DH_ + (lane & 3) * 2;
#pragma unroll
    for (int g = 0; g < 8; g++) {
        *(float2*)(ob + g * 8) = make_float2(O[g][0] * inv0, O[g][1] * inv0);
        *(float2*)(ob + 8 * INNER_ + g * 8) = make_float2(O[g][2] * inv1, O[g][3] * inv1);
    }
}

// ---------------------------------------------------------------------------
extern "C" void kernel_launch(void* const* d_in, const int* in_sizes, int n_in,
                              void* d_out, int out_size)
{
    (void)in_sizes; (void)n_in; (void)out_size;
    const float* x     = (const float*)d_in[0];
    const float* rot   = (const float*)d_in[1];
    const float* w_qkv = (const float*)d_in[2];
    const float* w_out = (const float*)d_in[3];
    const float* b_out = (const float*)d_in[4];
    float* out = (float*)d_out;

    float *p_qkv, *p_att;
    __nv_bfloat16 *p_ax, *p_bq, *p_bo;
    cudaGetSymbolAddress((void**)&p_qkv, g_qkv);
    cudaGetSymbolAddress((void**)&p_att, g_att);
    cudaGetSymbolAddress((void**)&p_ax, g_ax);
    cudaGetSymbolAddress((void**)&p_bq, g_bq);
    cudaGetSymbolAddress((void**)&p_bo, g_bo);

    cudaFuncSetAttribute(gemm_mma, cudaFuncAttributeMaxDynamicSharedMemorySize, GEMM_SMEM);
    cudaFuncSetAttribute(attn_mma, cudaFuncAttributeMaxDynamicSharedMemorySize, ATTN_SMEM);

    // 1) split x -> A' [4096, 2048], w_qkv -> B' [3072, 3072]
    split_kernel<<<(4096 * 256) / 256, 256>>>(x, p_ax, 4096 * 256, 0);
    split_kernel<<<(3072 * 256) / 256, 256>>>(w_qkv, p_bq, 3072 * 256, 1);

    // 2) QKV projection (tensor cores, fp32 accuracy via 3-term split)
    {
        dim3 grid(3072 / 128, 4096 / 128);
        gemm_mma<<<grid, 256, GEMM_SMEM>>>(p_ax, p_bq, p_qkv, nullptr, 3072);
    }

    // 3) RoPE + split to attention operand layouts
    rope_split_kernel<<<(32 * N_ * 32) / 256, 256>>>(rot);

    // 4) Attention (tensor cores, 3-term split S and PV, occ 2)
    {
        dim3 grid(N_ / 128, 32);
        attn_mma<<<grid, 256, ATTN_SMEM>>>();
    }

    // 5) split att -> A' [4096, 2048], w_out -> B' [1024, 3072]
    split_kernel<<<(4096 * 256) / 256, 256>>>(p_att, p_ax, 4096 * 256, 0);
    split_kernel<<<(1024 * 256) / 256, 256>>>(w_out, p_bo, 1024 * 256, 1);

    // 6) Output projection + bias (tensor cores)
    {
        dim3 grid(1024 / 128, 4096 / 128);
        gemm_mma<<<grid, 256, GEMM_SMEM>>>(p_ax, p_bo, out, b_out, 1024);
    }
}

// round 12
// speedup vs baseline: 1.2375x; 1.2375x over previous
#include <cuda_runtime.h>
#include <cuda_bf16.h>
#include <cuda_fp16.h>
#include <cstdint>

#define B_ 2
#define N_ 2048
#define DIM_ 1024
#define H_ 16
#define DH_ 64
#define INNER_ 1024
// SCALE * log2(e): softmax computed in base-2 domain
#define QSCALE_ (0.125f * 1.4426950408889634f)
#define KFULL_ 3072          // B-side split K = 3 * 1024
#define KA_ 2048             // A-side split K = 2 * 1024 (term 3 reuses hi)
#define NITER_ 96            // KFULL / 32

// ---------------------------------------------------------------------------
// Scratch (device globals: no cudaMalloc allowed)
// ---------------------------------------------------------------------------
__device__ float g_qkv[B_ * N_ * 3 * INNER_];   // [B,N,3*INNER]
__device__ float g_att[B_ * N_ * INNER_];       // [B,N,INNER]

// attention operands, fp16
__device__ __half g_qsh[32 * N_ * 64];          // [bh][n][q fp16] (scaled, log2e folded)
__device__ __half g_ksh[32 * N_ * 64];          // [bh][n][k fp16]
__device__ __half g_vhh[32 * N_ * 64];          // v hi (fp16)
__device__ __half g_vlh[32 * N_ * 64];          // v residual (fp16)

// bf16 split buffers for projection GEMMs
__device__ __nv_bfloat16 g_ax[4096 * KA_];      // activations [hi|lo]
__device__ __nv_bfloat16 g_bq[3072 * KFULL_];   // w_qkv split [hi|hi|lo]
__device__ __nv_bfloat16 g_bo[1024 * KFULL_];   // w_out split [hi|hi|lo]

// ---------------------------------------------------------------------------
// PTX helpers (arch-portable: compile under compute_103)
// ---------------------------------------------------------------------------
__device__ __forceinline__ uint32_t smem_to_u32(const void* p) {
    uint32_t a;
    asm("{ .reg .u64 t; cvta.to.shared.u64 t, %1; cvt.u32.u64 %0, t; }" : "=r"(a) : "l"(p));
    return a;
}
__device__ __forceinline__ void cp_async16(uint32_t dst, const void* src) {
    asm volatile("cp.async.cg.shared.global [%0], [%1], 16;\n" :: "r"(dst), "l"(src));
}
#define CP_COMMIT()  asm volatile("cp.async.commit_group;\n" ::: "memory")
#define CP_WAIT2()   asm volatile("cp.async.wait_group 2;\n" ::: "memory")
#define CP_WAIT1()   asm volatile("cp.async.wait_group 1;\n" ::: "memory")
#define CP_WAIT0()   asm volatile("cp.async.wait_group 0;\n" ::: "memory")

#define LDMATRIX_X4(r, addr) \
    asm volatile("ldmatrix.sync.aligned.m8n8.x4.shared.b16 {%0,%1,%2,%3}, [%4];" \
        : "=r"((r)[0]), "=r"((r)[1]), "=r"((r)[2]), "=r"((r)[3]) : "r"(addr))

#define LDMATRIX_X4_T(r, addr) \
    asm volatile("ldmatrix.sync.aligned.m8n8.x4.trans.shared.b16 {%0,%1,%2,%3}, [%4];" \
        : "=r"((r)[0]), "=r"((r)[1]), "=r"((r)[2]), "=r"((r)[3]) : "r"(addr))

// bf16 mma (projection GEMMs)
#define MMA16816(c, a, b0, b1) \
    asm volatile("mma.sync.aligned.m16n8k16.row.col.f32.bf16.bf16.f32 " \
        "{%0,%1,%2,%3}, {%4,%5,%6,%7}, {%8,%9}, {%0,%1,%2,%3};" \
        : "+f"((c)[0]), "+f"((c)[1]), "+f"((c)[2]), "+f"((c)[3]) \
        : "r"((a)[0]), "r"((a)[1]), "r"((a)[2]), "r"((a)[3]), "r"(b0), "r"(b1))

// fp16 mma (attention)
#define MMA16816H(c, a, b0, b1) \
    asm volatile("mma.sync.aligned.m16n8k16.row.col.f32.f16.f16.f32 " \
        "{%0,%1,%2,%3}, {%4,%5,%6,%7}, {%8,%9}, {%0,%1,%2,%3};" \
        : "+f"((c)[0]), "+f"((c)[1]), "+f"((c)[2]), "+f"((c)[3]) \
        : "r"((a)[0]), "r"((a)[1]), "r"((a)[2]), "r"((a)[3]), "r"(b0), "r"(b1))

// pack f16x2 from two fp32 (lo -> low half, hi -> high half), round-nearest
#define PACK_F16X2_RN(d, lo, hi) \
    asm("cvt.rn.f16x2.f32 %0, %1, %2;" : "=r"(d) : "f"(hi), "f"(lo))

// ---------------------------------------------------------------------------
// fp32 -> bf16 split conversion (projection GEMMs).
// modeB=1 (weights): 3-term rows [hi | hi | lo], stride KFULL_ (3072)
// modeB=0 (activations): 2-term rows [hi | lo], stride KA_ (2048)
// Term pairing in GEMM: (Ah,Bh), (Al,Bh), (Ah,Bl) — residual ~2^-16.
// ---------------------------------------------------------------------------
__global__ void split_kernel(const float* __restrict__ src, __nv_bfloat16* __restrict__ dst,
                             int total_quads, int modeB)
{
    int i = blockIdx.x * blockDim.x + threadIdx.x;
    if (i >= total_quads) return;
    int r = i >> 8;              // / 256  (K=1024 -> 256 quads per row)
    int c = (i & 255) << 2;
    float4 v = ((const float4*)src)[i];

    __nv_bfloat16 h0 = __float2bfloat16_rn(v.x), h1 = __float2bfloat16_rn(v.y);
    __nv_bfloat16 h2 = __float2bfloat16_rn(v.z), h3 = __float2bfloat16_rn(v.w);
    __nv_bfloat16 l0 = __float2bfloat16_rn(v.x - __bfloat162float(h0));
    __nv_bfloat16 l1 = __float2bfloat16_rn(v.y - __bfloat162float(h1));
    __nv_bfloat16 l2 = __float2bfloat16_rn(v.z - __bfloat162float(h2));
    __nv_bfloat16 l3 = __float2bfloat16_rn(v.w - __bfloat162float(h3));

    __nv_bfloat162 hA = __nv_bfloat162(h0, h1), hB = __nv_bfloat162(h2, h3);
    __nv_bfloat162 lA = __nv_bfloat162(l0, l1), lB = __nv_bfloat162(l2, l3);

    if (modeB) {
        size_t base = (size_t)r * KFULL_ + c;
        __nv_bfloat162* d0 = (__nv_bfloat162*)(dst + base);
        __nv_bfloat162* d1 = (__nv_bfloat162*)(dst + base + 1024);
        __nv_bfloat162* d2 = (__nv_bfloat162*)(dst + base + 2048);
        d0[0] = hA; d0[1] = hB;
        d1[0] = hA; d1[1] = hB;
        d2[0] = lA; d2[1] = lB;
    } else {
        size_t base = (size_t)r * KA_ + c;
        __nv_bfloat162* d0 = (__nv_bfloat162*)(dst + base);
        __nv_bfloat162* d1 = (__nv_bfloat162*)(dst + base + 1024);
        d0[0] = hA; d0[1] = hB;
        d1[0] = lA; d1[1] = lB;
    }
}

// ---------------------------------------------------------------------------
// mma.sync bf16 NT GEMM: C[m,n] = sum_k A[m,k']*B[n,k] (+bias)
// A: [M, 2048] (k' = k mod 2048: term 3 reuses A-hi), B: [Ncol, 3072].
// CTA tile 128x128, BK=32, 8 warps (64x32), 4-stage cp.async pipeline.
// ---------------------------------------------------------------------------
#define BK_ 32
#define ROWB_ 80
#define STAGE_ (128 * ROWB_ * 2)
#define GEMM_SMEM (4 * STAGE_)

__global__ __launch_bounds__(256, 2) void gemm_mma(
    const __nv_bfloat16* __restrict__ A, const __nv_bfloat16* __restrict__ Bm,
    float* __restrict__ C, const float* __restrict__ bias, int Ncol)
{
    extern __shared__ char smem_raw[];
    const uint32_t sb = smem_to_u32(smem_raw);

    const int tid = threadIdx.x;
    const int lane = tid & 31, wid = tid >> 5;
    const int bm = blockIdx.y * 128, bn = blockIdx.x * 128;
    const int wm = (wid >> 2) * 64, wn = (wid & 3) * 32;

    const __nv_bfloat16* Abase = A + (size_t)bm * KA_;
    const __nv_bfloat16* Bbase = Bm + (size_t)bn * KFULL_;

    const int lrow = tid >> 1;
    const int lhalfB = (tid & 1) * 32;
    const int lhalfE = (tid & 1) * 16;
    const uint32_t so = (uint32_t)(lrow * ROWB_ + lhalfB);

    const uint32_t a_off = (uint32_t)((wm + (lane & 15)) * ROWB_ + (lane >> 4) * 16);
    const uint32_t b_off = (uint32_t)((wn + ((lane >> 4) << 3) + (lane & 7)) * ROWB_
                                      + ((lane >> 3) & 1) * 16);

    float acc[4][4][4];
#pragma unroll
    for (int mi = 0; mi < 4; mi++)
#pragma unroll
        for (int ni = 0; ni < 4; ni++)
#pragma unroll
            for (int r = 0; r < 4; r++) acc[mi][ni][r] = 0.f;

    auto load_tile = [&](int it) {
        uint32_t sa = sb + (uint32_t)(it & 3) * STAGE_;
        uint32_t sbb = sa + 128 * ROWB_;
        int kA = (it & 63) * BK_;          // A k wraps at 2048
        const __nv_bfloat16* Ag = Abase + (size_t)lrow * KA_ + kA + lhalfE;
        const __nv_bfloat16* Bg = Bbase + (size_t)lrow * KFULL_ + it * BK_ + lhalfE;
        cp_async16(sa + so, Ag);
        cp_async16(sa + so + 16, Ag + 8);
        cp_async16(sbb + so, Bg);
        cp_async16(sbb + so + 16, Bg + 8);
        CP_COMMIT();
    };

    load_tile(0);
    load_tile(1);
    load_tile(2);

    for (int it = 0; it < NITER_; it++) {
        CP_WAIT2();
        __syncthreads();
        if (it + 3 < NITER_) load_tile(it + 3);

        uint32_t sa = sb + (uint32_t)(it & 3) * STAGE_;
        uint32_t sbb = sa + 128 * ROWB_;
#pragma unroll
        for (int ks = 0; ks < 2; ks++) {
            uint32_t af[4][4], bf[2][4];
#pragma unroll
            for (int mi = 0; mi < 4; mi++)
                LDMATRIX_X4(af[mi], sa + a_off + mi * (16 * ROWB_) + ks * 32);
#pragma unroll
            for (int nb = 0; nb < 2; nb++)
                LDMATRIX_X4(bf[nb], sbb + b_off + nb * (16 * ROWB_) + ks * 32);
#pragma unroll
            for (int mi = 0; mi < 4; mi++)
#pragma unroll
                for (int ni = 0; ni < 4; ni++)
                    MMA16816(acc[mi][ni], af[mi], bf[ni >> 1][(ni & 1) * 2],
                             bf[ni >> 1][(ni & 1) * 2 + 1]);
        }
    }

#pragma unroll
    for (int mi = 0; mi < 4; mi++) {
        int row = bm + wm + mi * 16 + (lane >> 2);
#pragma unroll
        for (int ni = 0; ni < 4; ni++) {
            int col = bn + wn + ni * 8 + (lane & 3) * 2;
            float b0 = 0.f, b1 = 0.f;
            if (bias) { b0 = bias[col]; b1 = bias[col + 1]; }
            float2 v0 = make_float2(acc[mi][ni][0] + b0, acc[mi][ni][1] + b1);
            float2 v1 = make_float2(acc[mi][ni][2] + b0, acc[mi][ni][3] + b1);
            *(float2*)(C + (size_t)row * Ncol + col) = v0;
            *(float2*)(C + (size_t)(row + 8) * Ncol + col) = v1;
        }
    }
}

// ---------------------------------------------------------------------------
// RoPE + fp16 convert: g_qkv -> g_qsh (q fp16, x QSCALE log2e), g_ksh (k fp16),
//                      g_vhh (v fp16 hi), g_vlh (v fp16 residual)
// ---------------------------------------------------------------------------
__global__ void rope_split_kernel(const float* __restrict__ rot)
{
    int idx = blockIdx.x * blockDim.x + threadIdx.x;  // 32*2048*32 threads
    int d = idx & 31;
    int n = (idx >> 5) & (N_ - 1);
    int bh = idx >> 16;
    int b = bh >> 4, h = bh & 15;

    const float* base = g_qkv + ((size_t)(b * N_ + n)) * (3 * INNER_) + h * DH_ + d;
    float p1 = rot[n * DH_ + d];
    float p2 = rot[n * DH_ + d + 32];
    float c1 = cosf(p1), s1 = sinf(p1);
    float c2 = cosf(p2), s2 = sinf(p2);

    float q1 = base[0], q2 = base[32];
    float k1 = base[INNER_], k2 = base[INNER_ + 32];
    float v1 = base[2 * INNER_], v2 = base[2 * INNER_ + 32];

    float qr1 = (q1 * c1 - q2 * s1) * QSCALE_;
    float qr2 = (q2 * c2 + q1 * s2) * QSCALE_;
    float kr1 = k1 * c1 - k2 * s1;
    float kr2 = k2 * c2 + k1 * s2;

    size_t o = ((size_t)bh * N_ + n) * 64 + d;
    g_qsh[o]      = __float2half_rn(qr1);
    g_qsh[o + 32] = __float2half_rn(qr2);
    g_ksh[o]      = __float2half_rn(kr1);
    g_ksh[o + 32] = __float2half_rn(kr2);

    __half vh1 = __float2half_rn(v1), vh2 = __float2half_rn(v2);
    g_vhh[o]      = vh1;
    g_vhh[o + 32] = vh2;
    g_vlh[o]      = __float2half_rn(v1 - __half2float(vh1));
    g_vlh[o + 32] = __float2half_rn(v2 - __half2float(vh2));
}

// ---------------------------------------------------------------------------
// Tensor-core flash attention (fp16).
// CTA: 128 q-rows (8 warps x 16), key tiles of 64, double-buffered cp.async.
// S = Q K^T single-term fp16 (logit err ~5e-4). Softmax in base-2, fp32.
// O += P*Vh + P*Vl (P single fp16, V 2-term fp16).
// Per tile per warp: 32 + 64 = 96 MMAs (was 192 with bf16 3-term).
// ---------------------------------------------------------------------------
#define KT_ 64                   // keys per tile
#define NT_ (N_ / KT_)           // 32 tiles
#define KROWB_ 144               // 64 fp16 = 128B + 16B pad
#define VROWB_ 144
#define AST_BYTES (3 * KT_ * 144)            // K + Vh + Vl = 27648
#define ATTN_SMEM (2 * AST_BYTES)            // 55296

__global__ __launch_bounds__(256, 2) void attn_mma()
{
    extern __shared__ char smem_raw[];
    const uint32_t sb = smem_to_u32(smem_raw);

    const int tid = threadIdx.x;
    const int lane = tid & 31, wid = tid >> 5;
    const int qt = blockIdx.x;       // q tile (16)
    const int bh = blockIdx.y;       // 32
    const int b = bh >> 4, h = bh & 15;

    const __half* Kg  = g_ksh + (size_t)bh * N_ * 64;
    const __half* Vhg = g_vhh + (size_t)bh * N_ * 64;
    const __half* Vlg = g_vlh + (size_t)bh * N_ * 64;

    auto load_tile = [&](int t) {
        uint32_t st = sb + (uint32_t)(t & 1) * AST_BYTES;
        uint32_t vh_st = st + KT_ * KROWB_;
        uint32_t vl_st = vh_st + KT_ * VROWB_;
        int kb = t * KT_;
#pragma unroll
        for (int j = 0; j < 2; j++) {
            int idx = tid + j * 256;      // 512 chunks each of K/Vh/Vl
            int row = idx >> 3, c = idx & 7;
            cp_async16(st + row * KROWB_ + c * 16, Kg + (size_t)(kb + row) * 64 + c * 8);
            cp_async16(vh_st + row * VROWB_ + c * 16, Vhg + (size_t)(kb + row) * 64 + c * 8);
            cp_async16(vl_st + row * VROWB_ + c * 16, Vlg + (size_t)(kb + row) * 64 + c * 8);
        }
        CP_COMMIT();
    };

    load_tile(0);

    // ---- Q fragments via direct LDG in mma A-frag layout (fp16, 64 cols) ----
    uint32_t af[4][4];
    {
        const __half* q0 = g_qsh
            + ((size_t)bh * N_ + qt * 128 + wid * 16 + (lane >> 2)) * 64 + (lane & 3) * 2;
        const __half* q8 = q0 + 8 * 64;
#pragma unroll
        for (int ks = 0; ks < 4; ks++) {
            af[ks][0] = *(const uint32_t*)(q0 + ks * 16);
            af[ks][1] = *(const uint32_t*)(q8 + ks * 16);
            af[ks][2] = *(const uint32_t*)(q0 + ks * 16 + 8);
            af[ks][3] = *(const uint32_t*)(q8 + ks * 16 + 8);
        }
    }

    float O[8][4];
#pragma unroll
    for (int g = 0; g < 8; g++)
#pragma unroll
        for (int r = 0; r < 4; r++) O[g][r] = 0.f;
    float m0 = -1e30f, m1 = -1e30f, l0 = 0.f, l1 = 0.f;

    const uint32_t kb_off = (uint32_t)((((lane >> 4) << 3) + (lane & 7)) * KROWB_
                                       + ((lane >> 3) & 1) * 16);
    const uint32_t v_off = (uint32_t)((((lane >> 3) & 1) * 8 + (lane & 7)) * VROWB_
                                      + ((lane >> 4) << 3) * 2);

    for (int t = 0; t < NT_; t++) {
        if (t + 1 < NT_) { load_tile(t + 1); CP_WAIT1(); } else { CP_WAIT0(); }
        __syncthreads();

        uint32_t st = sb + (uint32_t)(t & 1) * AST_BYTES;
        uint32_t vh_st = st + KT_ * KROWB_;
        uint32_t vl_st = vh_st + KT_ * VROWB_;

        // ---- S = Q K^T : 8 key-blocks x 4 k-steps (fp16 single-term) ----
        float S[8][4];
#pragma unroll
        for (int g = 0; g < 8; g++)
#pragma unroll
            for (int r = 0; r < 4; r++) S[g][r] = 0.f;

#pragma unroll
        for (int ks = 0; ks < 4; ks++) {
            uint32_t kf[4][4];
#pragma unroll
            for (int g = 0; g < 4; g++)
                LDMATRIX_X4(kf[g], st + kb_off + g * (16 * KROWB_) + ks * 32);
#pragma unroll
            for (int g = 0; g < 4; g++) {
                MMA16816H(S[2 * g],     af[ks], kf[g][0], kf[g][1]);
                MMA16816H(S[2 * g + 1], af[ks], kf[g][2], kf[g][3]);
            }
        }

        // ---- online softmax (base-2 domain, fp32) ----
        float mx0 = -1e30f, mx1 = -1e30f;
#pragma unroll
        for (int g = 0; g < 8; g++) {
            mx0 = fmaxf(mx0, fmaxf(S[g][0], S[g][1]));
            mx1 = fmaxf(mx1, fmaxf(S[g][2], S[g][3]));
        }
        mx0 = fmaxf(mx0, __shfl_xor_sync(0xffffffffu, mx0, 1));
        mx0 = fmaxf(mx0, __shfl_xor_sync(0xffffffffu, mx0, 2));
        mx1 = fmaxf(mx1, __shfl_xor_sync(0xffffffffu, mx1, 1));
        mx1 = fmaxf(mx1, __shfl_xor_sync(0xffffffffu, mx1, 2));

        float m0n = fmaxf(m0, mx0), m1n = fmaxf(m1, mx1);
        float corr0 = exp2f(m0 - m0n), corr1 = exp2f(m1 - m1n);
        m0 = m0n; m1 = m1n;
        l0 *= corr0; l1 *= corr1;

#pragma unroll
        for (int g = 0; g < 8; g++) {
            S[g][0] = exp2f(S[g][0] - m0);
            S[g][1] = exp2f(S[g][1] - m0);
            S[g][2] = exp2f(S[g][2] - m1);
            S[g][3] = exp2f(S[g][3] - m1);
            l0 += S[g][0] + S[g][1];
            l1 += S[g][2] + S[g][3];
            O[g][0] *= corr0; O[g][1] *= corr0;
            O[g][2] *= corr1; O[g][3] *= corr1;
        }

        // ---- O += P * (Vh + Vl) : 4 k-steps over keys, P single fp16 ----
#pragma unroll
        for (int ks = 0; ks < 4; ks++) {
            uint32_t ph[4];
            PACK_F16X2_RN(ph[0], S[2 * ks][0],     S[2 * ks][1]);
            PACK_F16X2_RN(ph[1], S[2 * ks][2],     S[2 * ks][3]);
            PACK_F16X2_RN(ph[2], S[2 * ks + 1][0], S[2 * ks + 1][1]);
            PACK_F16X2_RN(ph[3], S[2 * ks + 1][2], S[2 * ks + 1][3]);
#pragma unroll
            for (int g = 0; g < 4; g++) {
                uint32_t vh[4], vl[4];
                LDMATRIX_X4_T(vh, vh_st + v_off + ks * (16 * VROWB_) + g * 32);
                LDMATRIX_X4_T(vl, vl_st + v_off + ks * (16 * VROWB_) + g * 32);
                MMA16816H(O[2 * g],     ph, vh[0], vh[1]);
                MMA16816H(O[2 * g + 1], ph, vh[2], vh[3]);
                MMA16816H(O[2 * g],     ph, vl[0], vl[1]);
                MMA16816H(O[2 * g + 1], ph, vl[2], vl[3]);
            }
        }
        __syncthreads();
    }

    // ---- finalize ----
    l0 += __shfl_xor_sync(0xffffffffu, l0, 1);
    l0 += __shfl_xor_sync(0xffffffffu, l0, 2);
    l1 += __shfl_xor_sync(0xffffffffu, l1, 1);
    l1 += __shfl_xor_sync(0xffffffffu, l1, 2);
    float inv0 = 1.f / l0, inv1 = 1.f / l1;

    int row = qt * 128 + wid * 16 + (lane >> 2);
    float* ob = g_att + ((size_t)b * N_ + row) * INNER_ + h * DH_ + (lane & 3) * 2;
#pragma unroll
    for (int g = 0; g < 8; g++) {
        *(float2*)(ob + g * 8) = make_float2(O[g][0] * inv0, O[g][1] * inv0);
        *(float2*)(ob + 8 * INNER_ + g * 8) = make_float2(O[g][2] * inv1, O[g][3] * inv1);
    }
}

// ---------------------------------------------------------------------------
extern "C" void kernel_launch(void* const* d_in, const int* in_sizes, int n_in,
                              void* d_out, int out_size)
{
    (void)in_sizes; (void)n_in; (void)out_size;
    const float* x     = (const float*)d_in[0];
    const float* rot   = (const float*)d_in[1];
    const float* w_qkv = (const float*)d_in[2];
    const float* w_out = (const float*)d_in[3];
    const float* b_out = (const float*)d_in[4];
    float* out = (float*)d_out;

    float *p_qkv, *p_att;
    __nv_bfloat16 *p_ax, *p_bq, *p_bo;
    cudaGetSymbolAddress((void**)&p_qkv, g_qkv);
    cudaGetSymbolAddress((void**)&p_att, g_att);
    cudaGetSymbolAddress((void**)&p_ax, g_ax);
    cudaGetSymbolAddress((void**)&p_bq, g_bq);
    cudaGetSymbolAddress((void**)&p_bo, g_bo);

    cudaFuncSetAttribute(gemm_mma, cudaFuncAttributeMaxDynamicSharedMemorySize, GEMM_SMEM);
    cudaFuncSetAttribute(attn_mma, cudaFuncAttributeMaxDynamicSharedMemorySize, ATTN_SMEM);

    // 1) split x -> A' [4096, 2048], w_qkv -> B' [3072, 3072]
    split_kernel<<<(4096 * 256) / 256, 256>>>(x, p_ax, 4096 * 256, 0);
    split_kernel<<<(3072 * 256) / 256, 256>>>(w_qkv, p_bq, 3072 * 256, 1);

    // 2) QKV projection (tensor cores, fp32 accuracy via 3-term split)
    {
        dim3 grid(3072 / 128, 4096 / 128);
        gemm_mma<<<grid, 256, GEMM_SMEM>>>(p_ax, p_bq, p_qkv, nullptr, 3072);
    }

    // 3) RoPE + fp16 convert to attention operand layouts
    rope_split_kernel<<<(32 * N_ * 32) / 256, 256>>>(rot);

    // 4) Attention (tensor cores, fp16)
    {
        dim3 grid(N_ / 128, 32);
        attn_mma<<<grid, 256, ATTN_SMEM>>>();
    }

    // 5) split att -> A' [4096, 2048], w_out -> B' [1024, 3072]
    split_kernel<<<(4096 * 256) / 256, 256>>>(p_att, p_ax, 4096 * 256, 0);
    split_kernel<<<(1024 * 256) / 256, 256>>>(w_out, p_bo, 1024 * 256, 1);

    // 6) Output projection + bias (tensor cores)
    {
        dim3 grid(1024 / 128, 4096 / 128);
        gemm_mma<<<grid, 256, GEMM_SMEM>>>(p_ax, p_bo, out, b_out, 1024);
    }
}

// round 14
// speedup vs baseline: 1.7927x; 1.4487x over previous
#include <cuda_runtime.h>
#include <cuda_bf16.h>
#include <cuda_fp16.h>
#include <cstdint>

#define B_ 2
#define N_ 2048
#define DIM_ 1024
#define H_ 16
#define DH_ 64
#define INNER_ 1024
// SCALE * log2(e): softmax computed in base-2 domain
#define QSCALE_ (0.125f * 1.4426950408889634f)
#define KA_ 2048             // A-side split K = 2 * 1024 ([Ah|Al])
#define KB_ 1024             // B-side K (single fp16, GEMM wraps k at 1024)
#define NITER_ 64            // KA_ / 32

// ---------------------------------------------------------------------------
// Scratch (device globals: no cudaMalloc allowed)
// ---------------------------------------------------------------------------
__device__ float g_qkv[B_ * N_ * 3 * INNER_];   // [B,N,3*INNER]
__device__ float g_att[B_ * N_ * INNER_];       // [B,N,INNER]

// attention operands, fp16
__device__ __half g_qsh[32 * N_ * 64];          // [bh][n][q fp16] (scaled, log2e folded)
__device__ __half g_ksh[32 * N_ * 64];          // [bh][n][k fp16]
__device__ __half g_vhh[32 * N_ * 64];          // v (fp16)

// fp16 buffers for projection GEMMs
__device__ __half g_ax[4096 * KA_];             // activations [Ah|Al]
__device__ __half g_bq[3072 * KB_];             // w_qkv fp16
__device__ __half g_bo[1024 * KB_];             // w_out fp16

// ---------------------------------------------------------------------------
// PTX helpers (arch-portable: compile under compute_103)
// ---------------------------------------------------------------------------
__device__ __forceinline__ uint32_t smem_to_u32(const void* p) {
    uint32_t a;
    asm("{ .reg .u64 t; cvta.to.shared.u64 t, %1; cvt.u32.u64 %0, t; }" : "=r"(a) : "l"(p));
    return a;
}
__device__ __forceinline__ void cp_async16(uint32_t dst, const void* src) {
    asm volatile("cp.async.cg.shared.global [%0], [%1], 16;\n" :: "r"(dst), "l"(src));
}
#define CP_COMMIT()  asm volatile("cp.async.commit_group;\n" ::: "memory")
#define CP_WAIT2()   asm volatile("cp.async.wait_group 2;\n" ::: "memory")
#define CP_WAIT1()   asm volatile("cp.async.wait_group 1;\n" ::: "memory")
#define CP_WAIT0()   asm volatile("cp.async.wait_group 0;\n" ::: "memory")

#define LDMATRIX_X4(r, addr) \
    asm volatile("ldmatrix.sync.aligned.m8n8.x4.shared.b16 {%0,%1,%2,%3}, [%4];" \
        : "=r"((r)[0]), "=r"((r)[1]), "=r"((r)[2]), "=r"((r)[3]) : "r"(addr))

#define LDMATRIX_X4_T(r, addr) \
    asm volatile("ldmatrix.sync.aligned.m8n8.x4.trans.shared.b16 {%0,%1,%2,%3}, [%4];" \
        : "=r"((r)[0]), "=r"((r)[1]), "=r"((r)[2]), "=r"((r)[3]) : "r"(addr))

// fp16 mma
#define MMA16816H(c, a, b0, b1) \
    asm volatile("mma.sync.aligned.m16n8k16.row.col.f32.f16.f16.f32 " \
        "{%0,%1,%2,%3}, {%4,%5,%6,%7}, {%8,%9}, {%0,%1,%2,%3};" \
        : "+f"((c)[0]), "+f"((c)[1]), "+f"((c)[2]), "+f"((c)[3]) \
        : "r"((a)[0]), "r"((a)[1]), "r"((a)[2]), "r"((a)[3]), "r"(b0), "r"(b1))

// pack f16x2 from two fp32 (lo -> low half, hi -> high half), round-nearest
#define PACK_F16X2_RN(d, lo, hi) \
    asm("cvt.rn.f16x2.f32 %0, %1, %2;" : "=r"(d) : "f"(hi), "f"(lo))

// ---------------------------------------------------------------------------
// fp32 -> fp16 conversion for projection GEMMs.
// modeB=1 (weights): single fp16, stride KB_ (1024)
// modeB=0 (activations): 2-term [Ah | Al], stride KA_ (2048)
// GEMM computes (Ah+Al)*Bh = A*Bh; dropped A*Bl term ~1.4e-4 rms.
// ---------------------------------------------------------------------------
__global__ void split_kernel(const float* __restrict__ src, __half* __restrict__ dst,
                             int total_quads, int modeB)
{
    int i = blockIdx.x * blockDim.x + threadIdx.x;
    if (i >= total_quads) return;
    int r = i >> 8;              // / 256  (K=1024 -> 256 quads per row)
    int c = (i & 255) << 2;
    float4 v = ((const float4*)src)[i];

    __half h0 = __float2half_rn(v.x), h1 = __float2half_rn(v.y);
    __half h2 = __float2half_rn(v.z), h3 = __float2half_rn(v.w);

    if (modeB) {
        size_t base = (size_t)r * KB_ + c;
        __half2* d0 = (__half2*)(dst + base);
        d0[0] = __half2(h0, h1); d0[1] = __half2(h2, h3);
    } else {
        __half l0 = __float2half_rn(v.x - __half2float(h0));
        __half l1 = __float2half_rn(v.y - __half2float(h1));
        __half l2 = __float2half_rn(v.z - __half2float(h2));
        __half l3 = __float2half_rn(v.w - __half2float(h3));
        size_t base = (size_t)r * KA_ + c;
        __half2* d0 = (__half2*)(dst + base);
        __half2* d1 = (__half2*)(dst + base + 1024);
        d0[0] = __half2(h0, h1); d0[1] = __half2(h2, h3);
        d1[0] = __half2(l0, l1); d1[1] = __half2(l2, l3);
    }
}

// ---------------------------------------------------------------------------
// mma.sync fp16 NT GEMM: C[m,n] = sum_k A[m,k]*B[n,k mod 1024] (+bias)
// A: [M, 2048] = [Ah|Al], B: [Ncol, 1024] fp16.
// CTA tile 128x128, BK=32, 8 warps (64x32), 4-stage cp.async pipeline.
// ---------------------------------------------------------------------------
#define BK_ 32
#define ROWB_ 80
#define STAGE_ (128 * ROWB_ * 2)
#define GEMM_SMEM (4 * STAGE_)

__global__ __launch_bounds__(256, 2) void gemm_mma(
    const __half* __restrict__ A, const __half* __restrict__ Bm,
    float* __restrict__ C, const float* __restrict__ bias, int Ncol)
{
    extern __shared__ char smem_raw[];
    const uint32_t sb = smem_to_u32(smem_raw);

    const int tid = threadIdx.x;
    const int lane = tid & 31, wid = tid >> 5;
    const int bm = blockIdx.y * 128, bn = blockIdx.x * 128;
    const int wm = (wid >> 2) * 64, wn = (wid & 3) * 32;

    const __half* Abase = A + (size_t)bm * KA_;
    const __half* Bbase = Bm + (size_t)bn * KB_;

    const int lrow = tid >> 1;
    const int lhalfB = (tid & 1) * 32;
    const int lhalfE = (tid & 1) * 16;
    const uint32_t so = (uint32_t)(lrow * ROWB_ + lhalfB);

    const uint32_t a_off = (uint32_t)((wm + (lane & 15)) * ROWB_ + (lane >> 4) * 16);
    const uint32_t b_off = (uint32_t)((wn + ((lane >> 4) << 3) + (lane & 7)) * ROWB_
                                      + ((lane >> 3) & 1) * 16);

    float acc[4][4][4];
#pragma unroll
    for (int mi = 0; mi < 4; mi++)
#pragma unroll
        for (int ni = 0; ni < 4; ni++)
#pragma unroll
            for (int r = 0; r < 4; r++) acc[mi][ni][r] = 0.f;

    auto load_tile = [&](int it) {
        uint32_t sa = sb + (uint32_t)(it & 3) * STAGE_;
        uint32_t sbb = sa + 128 * ROWB_;
        int kB = (it & 31) * BK_;          // B k wraps at 1024
        const __half* Ag = Abase + (size_t)lrow * KA_ + it * BK_ + lhalfE;
        const __half* Bg = Bbase + (size_t)lrow * KB_ + kB + lhalfE;
        cp_async16(sa + so, Ag);
        cp_async16(sa + so + 16, Ag + 8);
        cp_async16(sbb + so, Bg);
        cp_async16(sbb + so + 16, Bg + 8);
        CP_COMMIT();
    };

    load_tile(0);
    load_tile(1);
    load_tile(2);

    for (int it = 0; it < NITER_; it++) {
        CP_WAIT2();
        __syncthreads();
        if (it + 3 < NITER_) load_tile(it + 3);

        uint32_t sa = sb + (uint32_t)(it & 3) * STAGE_;
        uint32_t sbb = sa + 128 * ROWB_;
#pragma unroll
        for (int ks = 0; ks < 2; ks++) {
            uint32_t af[4][4], bf[2][4];
#pragma unroll
            for (int mi = 0; mi < 4; mi++)
                LDMATRIX_X4(af[mi], sa + a_off + mi * (16 * ROWB_) + ks * 32);
#pragma unroll
            for (int nb = 0; nb < 2; nb++)
                LDMATRIX_X4(bf[nb], sbb + b_off + nb * (16 * ROWB_) + ks * 32);
#pragma unroll
            for (int mi = 0; mi < 4; mi++)
#pragma unroll
                for (int ni = 0; ni < 4; ni++)
                    MMA16816H(acc[mi][ni], af[mi], bf[ni >> 1][(ni & 1) * 2],
                              bf[ni >> 1][(ni & 1) * 2 + 1]);
        }
    }

#pragma unroll
    for (int mi = 0; mi < 4; mi++) {
        int row = bm + wm + mi * 16 + (lane >> 2);
#pragma unroll
        for (int ni = 0; ni < 4; ni++) {
            int col = bn + wn + ni * 8 + (lane & 3) * 2;
            float b0 = 0.f, b1 = 0.f;
            if (bias) { b0 = bias[col]; b1 = bias[col + 1]; }
            float2 v0 = make_float2(acc[mi][ni][0] + b0, acc[mi][ni][1] + b1);
            float2 v1 = make_float2(acc[mi][ni][2] + b0, acc[mi][ni][3] + b1);
            *(float2*)(C + (size_t)row * Ncol + col) = v0;
            *(float2*)(C + (size_t)(row + 8) * Ncol + col) = v1;
        }
    }
}

// ---------------------------------------------------------------------------
// RoPE + fp16 convert: g_qkv -> g_qsh (q fp16, x QSCALE log2e), g_ksh, g_vhh
// ---------------------------------------------------------------------------
__global__ void rope_split_kernel(const float* __restrict__ rot)
{
    int idx = blockIdx.x * blockDim.x + threadIdx.x;  // 32*2048*32 threads
    int d = idx & 31;
    int n = (idx >> 5) & (N_ - 1);
    int bh = idx >> 16;
    int b = bh >> 4, h = bh & 15;

    const float* base = g_qkv + ((size_t)(b * N_ + n)) * (3 * INNER_) + h * DH_ + d;
    float p1 = rot[n * DH_ + d];
    float p2 = rot[n * DH_ + d + 32];
    float c1 = cosf(p1), s1 = sinf(p1);
    float c2 = cosf(p2), s2 = sinf(p2);

    float q1 = base[0], q2 = base[32];
    float k1 = base[INNER_], k2 = base[INNER_ + 32];
    float v1 = base[2 * INNER_], v2 = base[2 * INNER_ + 32];

    float qr1 = (q1 * c1 - q2 * s1) * QSCALE_;
    float qr2 = (q2 * c2 + q1 * s2) * QSCALE_;
    float kr1 = k1 * c1 - k2 * s1;
    float kr2 = k2 * c2 + k1 * s2;

    size_t o = ((size_t)bh * N_ + n) * 64 + d;
    g_qsh[o]      = __float2half_rn(qr1);
    g_qsh[o + 32] = __float2half_rn(qr2);
    g_ksh[o]      = __float2half_rn(kr1);
    g_ksh[o + 32] = __float2half_rn(kr2);
    g_vhh[o]      = __float2half_rn(v1);
    g_vhh[o + 32] = __float2half_rn(v2);
}

// ---------------------------------------------------------------------------
// Tensor-core flash attention (fp16).
// CTA: 128 q-rows (8 warps x 16), key tiles of 64, double-buffered cp.async.
// S = Q K^T single fp16; O += P*V single fp16. Softmax in base-2, fp32.
// Per tile per warp: 32 + 32 = 64 MMAs.
// ---------------------------------------------------------------------------
#define KT_ 64                   // keys per tile
#define NT_ (N_ / KT_)           // 32 tiles
#define KROWB_ 144               // 64 fp16 = 128B + 16B pad
#define VROWB_ 144
#define AST_BYTES (2 * KT_ * 144)            // K + V = 18432
#define ATTN_SMEM (2 * AST_BYTES)            // 36864

__global__ __launch_bounds__(256, 2) void attn_mma()
{
    extern __shared__ char smem_raw[];
    const uint32_t sb = smem_to_u32(smem_raw);

    const int tid = threadIdx.x;
    const int lane = tid & 31, wid = tid >> 5;
    const int qt = blockIdx.x;       // q tile (16)
    const int bh = blockIdx.y;       // 32
    const int b = bh >> 4, h = bh & 15;

    const __half* Kg = g_ksh + (size_t)bh * N_ * 64;
    const __half* Vg = g_vhh + (size_t)bh * N_ * 64;

    auto load_tile = [&](int t) {
        uint32_t st = sb + (uint32_t)(t & 1) * AST_BYTES;
        uint32_t v_st = st + KT_ * KROWB_;
        int kb = t * KT_;
#pragma unroll
        for (int j = 0; j < 2; j++) {
            int idx = tid + j * 256;      // 512 chunks each of K/V
            int row = idx >> 3, c = idx & 7;
            cp_async16(st + row * KROWB_ + c * 16, Kg + (size_t)(kb + row) * 64 + c * 8);
            cp_async16(v_st + row * VROWB_ + c * 16, Vg + (size_t)(kb + row) * 64 + c * 8);
        }
        CP_COMMIT();
    };

    load_tile(0);

    // ---- Q fragments via direct LDG in mma A-frag layout (fp16, 64 cols) ----
    uint32_t af[4][4];
    {
        const __half* q0 = g_qsh
            + ((size_t)bh * N_ + qt * 128 + wid * 16 + (lane >> 2)) * 64 + (lane & 3) * 2;
        const __half* q8 = q0 + 8 * 64;
#pragma unroll
        for (int ks = 0; ks < 4; ks++) {
            af[ks][0] = *(const uint32_t*)(q0 + ks * 16);
            af[ks][1] = *(const uint32_t*)(q8 + ks * 16);
            af[ks][2] = *(const uint32_t*)(q0 + ks * 16 + 8);
            af[ks][3] = *(const uint32_t*)(q8 + ks * 16 + 8);
        }
    }

    float O[8][4];
#pragma unroll
    for (int g = 0; g < 8; g++)
#pragma unroll
        for (int r = 0; r < 4; r++) O[g][r] = 0.f;
    float m0 = -1e30f, m1 = -1e30f, l0 = 0.f, l1 = 0.f;

    const uint32_t kb_off = (uint32_t)((((lane >> 4) << 3) + (lane & 7)) * KROWB_
                                       + ((lane >> 3) & 1) * 16);
    const uint32_t v_off = (uint32_t)((((lane >> 3) & 1) * 8 + (lane & 7)) * VROWB_
                                      + ((lane >> 4) << 3) * 2);

    for (int t = 0; t < NT_; t++) {
        if (t + 1 < NT_) { load_tile(t + 1); CP_WAIT1(); } else { CP_WAIT0(); }
        __syncthreads();

        uint32_t st = sb + (uint32_t)(t & 1) * AST_BYTES;
        uint32_t v_st = st + KT_ * KROWB_;

        // ---- S = Q K^T : 8 key-blocks x 4 k-steps ----
        float S[8][4];
#pragma unroll
        for (int g = 0; g < 8; g++)
#pragma unroll
            for (int r = 0; r < 4; r++) S[g][r] = 0.f;

#pragma unroll
        for (int ks = 0; ks < 4; ks++) {
            uint32_t kf[4][4];
#pragma unroll
            for (int g = 0; g < 4; g++)
                LDMATRIX_X4(kf[g], st + kb_off + g * (16 * KROWB_) + ks * 32);
#pragma unroll
            for (int g = 0; g < 4; g++) {
                MMA16816H(S[2 * g],     af[ks], kf[g][0], kf[g][1]);
                MMA16816H(S[2 * g + 1], af[ks], kf[g][2], kf[g][3]);
            }
        }

        // ---- online softmax (base-2 domain, fp32) ----
        float mx0 = -1e30f, mx1 = -1e30f;
#pragma unroll
        for (int g = 0; g < 8; g++) {
            mx0 = fmaxf(mx0, fmaxf(S[g][0], S[g][1]));
            mx1 = fmaxf(mx1, fmaxf(S[g][2], S[g][3]));
        }
        mx0 = fmaxf(mx0, __shfl_xor_sync(0xffffffffu, mx0, 1));
        mx0 = fmaxf(mx0, __shfl_xor_sync(0xffffffffu, mx0, 2));
        mx1 = fmaxf(mx1, __shfl_xor_sync(0xffffffffu, mx1, 1));
        mx1 = fmaxf(mx1, __shfl_xor_sync(0xffffffffu, mx1, 2));

        float m0n = fmaxf(m0, mx0), m1n = fmaxf(m1, mx1);
        float corr0 = exp2f(m0 - m0n), corr1 = exp2f(m1 - m1n);
        m0 = m0n; m1 = m1n;
        l0 *= corr0; l1 *= corr1;

#pragma unroll
        for (int g = 0; g < 8; g++) {
            S[g][0] = exp2f(S[g][0] - m0);
            S[g][1] = exp2f(S[g][1] - m0);
            S[g][2] = exp2f(S[g][2] - m1);
            S[g][3] = exp2f(S[g][3] - m1);
            l0 += S[g][0] + S[g][1];
            l1 += S[g][2] + S[g][3];
            O[g][0] *= corr0; O[g][1] *= corr0;
            O[g][2] *= corr1; O[g][3] *= corr1;
        }

        // ---- O += P * V : 4 k-steps over keys, P single fp16 ----
#pragma unroll
        for (int ks = 0; ks < 4; ks++) {
            uint32_t ph[4];
            PACK_F16X2_RN(ph[0], S[2 * ks][0],     S[2 * ks][1]);
            PACK_F16X2_RN(ph[1], S[2 * ks][2],     S[2 * ks][3]);
            PACK_F16X2_RN(ph[2], S[2 * ks + 1][0], S[2 * ks + 1][1]);
            PACK_F16X2_RN(ph[3], S[2 * ks + 1][2], S[2 * ks + 1][3]);
#pragma unroll
            for (int g = 0; g < 4; g++) {
                uint32_t vf[4];
                LDMATRIX_X4_T(vf, v_st + v_off + ks * (16 * VROWB_) + g * 32);
                MMA16816H(O[2 * g],     ph, vf[0], vf[1]);
                MMA16816H(O[2 * g + 1], ph, vf[2], vf[3]);
            }
        }
        __syncthreads();
    }

    // ---- finalize ----
    l0 += __shfl_xor_sync(0xffffffffu, l0, 1);
    l0 += __shfl_xor_sync(0xffffffffu, l0, 2);
    l1 += __shfl_xor_sync(0xffffffffu, l1, 1);
    l1 += __shfl_xor_sync(0xffffffffu, l1, 2);
    float inv0 = 1.f / l0, inv1 = 1.f / l1;

    int row = qt * 128 + wid * 16 + (lane >> 2);
    float* ob = g_att + ((size_t)b * N_ + row) * INNER_ + h * DH_ + (lane & 3) * 2;
#pragma unroll
    for (int g = 0; g < 8; g++) {
        *(float2*)(ob + g * 8) = make_float2(O[g][0] * inv0, O[g][1] * inv0);
        *(float2*)(ob + 8 * INNER_ + g * 8) = make_float2(O[g][2] * inv1, O[g][3] * inv1);
    }
}

// ---------------------------------------------------------------------------
extern "C" void kernel_launch(void* const* d_in, const int* in_sizes, int n_in,
                              void* d_out, int out_size)
{
    (void)in_sizes; (void)n_in; (void)out_size;
    const float* x     = (const float*)d_in[0];
    const float* rot   = (const float*)d_in[1];
    const float* w_qkv = (const float*)d_in[2];
    const float* w_out = (const float*)d_in[3];
    const float* b_out = (const float*)d_in[4];
    float* out = (float*)d_out;

    float *p_qkv, *p_att;
    __half *p_ax, *p_bq, *p_bo;
    cudaGetSymbolAddress((void**)&p_qkv, g_qkv);
    cudaGetSymbolAddress((void**)&p_att, g_att);
    cudaGetSymbolAddress((void**)&p_ax, g_ax);
    cudaGetSymbolAddress((void**)&p_bq, g_bq);
    cudaGetSymbolAddress((void**)&p_bo, g_bo);

    cudaFuncSetAttribute(gemm_mma, cudaFuncAttributeMaxDynamicSharedMemorySize, GEMM_SMEM);
    cudaFuncSetAttribute(attn_mma, cudaFuncAttributeMaxDynamicSharedMemorySize, ATTN_SMEM);

    // 1) split x -> A' [4096, 2048] ([Ah|Al]), convert w_qkv -> fp16 [3072, 1024]
    split_kernel<<<(4096 * 256) / 256, 256>>>(x, p_ax, 4096 * 256, 0);
    split_kernel<<<(3072 * 256) / 256, 256>>>(w_qkv, p_bq, 3072 * 256, 1);

    // 2) QKV projection (fp16 tensor cores, 2-term compensated)
    {
        dim3 grid(3072 / 128, 4096 / 128);
        gemm_mma<<<grid, 256, GEMM_SMEM>>>(p_ax, p_bq, p_qkv, nullptr, 3072);
    }

    // 3) RoPE + fp16 convert to attention operand layouts
    rope_split_kernel<<<(32 * N_ * 32) / 256, 256>>>(rot);

    // 4) Attention (fp16 tensor cores)
    {
        dim3 grid(N_ / 128, 32);
        attn_mma<<<grid, 256, ATTN_SMEM>>>();
    }

    // 5) split att -> A' [4096, 2048], convert w_out -> fp16 [1024, 1024]
    split_kernel<<<(4096 * 256) / 256, 256>>>(p_att, p_ax, 4096 * 256, 0);
    split_kernel<<<(1024 * 256) / 256, 256>>>(w_out, p_bo, 1024 * 256, 1);

    // 6) Output projection + bias (fp16 tensor cores)
    {
        dim3 grid(1024 / 128, 4096 / 128);
        gemm_mma<<<grid, 256, GEMM_SMEM>>>(p_ax, p_bo, out, b_out, 1024);
    }
}

// round 17
// speedup vs baseline: 1.8466x; 1.0301x over previous
#include <cuda_runtime.h>
#include <cuda_bf16.h>
#include <cuda_fp16.h>
#include <cstdint>

#define B_ 2
#define N_ 2048
#define DIM_ 1024
#define H_ 16
#define DH_ 64
#define INNER_ 1024
// SCALE * log2(e): softmax computed in base-2 domain
#define QSCALE_ (0.125f * 1.4426950408889634f)
#define KA_ 2048             // A-side split K = 2 * 1024 ([Ah|Al])
#define KB_ 1024             // B-side K (single fp16, GEMM wraps k at 1024)
#define NITER_ 64            // KA_ / 32

// ---------------------------------------------------------------------------
// Scratch (device globals: no cudaMalloc allowed)
// ---------------------------------------------------------------------------
// attention operands, fp16 (written directly by the QKV GEMM epilogue)
__device__ __half g_qsh[32 * N_ * 64];          // [bh][n][q fp16] (scaled, log2e folded)
__device__ __half g_ksh[32 * N_ * 64];          // [bh][n][k fp16]
__device__ __half g_vhh[32 * N_ * 64];          // v (fp16)

// fp16 buffers for projection GEMMs
__device__ __half g_ax[4096 * KA_];             // activations [Ah|Al]
__device__ __half g_bq[3072 * KB_];             // w_qkv fp16
__device__ __half g_bo[1024 * KB_];             // w_out fp16

// rope table: [n][d<32] = (cos p_d, sin p_d, cos p_{d+32}, sin p_{d+32})
__device__ float4 g_rtab[N_ * 32];

// ---------------------------------------------------------------------------
// PTX helpers (arch-portable: compile under compute_103)
// ---------------------------------------------------------------------------
__device__ __forceinline__ uint32_t smem_to_u32(const void* p) {
    uint32_t a;
    asm("{ .reg .u64 t; cvta.to.shared.u64 t, %1; cvt.u32.u64 %0, t; }" : "=r"(a) : "l"(p));
    return a;
}
__device__ __forceinline__ void cp_async16(uint32_t dst, const void* src) {
    asm volatile("cp.async.cg.shared.global [%0], [%1], 16;\n" :: "r"(dst), "l"(src));
}
#define CP_COMMIT()  asm volatile("cp.async.commit_group;\n" ::: "memory")
#define CP_WAIT2()   asm volatile("cp.async.wait_group 2;\n" ::: "memory")
#define CP_WAIT1()   asm volatile("cp.async.wait_group 1;\n" ::: "memory")
#define CP_WAIT0()   asm volatile("cp.async.wait_group 0;\n" ::: "memory")

#define LDMATRIX_X4(r, addr) \
    asm volatile("ldmatrix.sync.aligned.m8n8.x4.shared.b16 {%0,%1,%2,%3}, [%4];" \
        : "=r"((r)[0]), "=r"((r)[1]), "=r"((r)[2]), "=r"((r)[3]) : "r"(addr))

#define LDMATRIX_X4_T(r, addr) \
    asm volatile("ldmatrix.sync.aligned.m8n8.x4.trans.shared.b16 {%0,%1,%2,%3}, [%4];" \
        : "=r"((r)[0]), "=r"((r)[1]), "=r"((r)[2]), "=r"((r)[3]) : "r"(addr))

// fp16 mma
#define MMA16816H(c, a, b0, b1) \
    asm volatile("mma.sync.aligned.m16n8k16.row.col.f32.f16.f16.f32 " \
        "{%0,%1,%2,%3}, {%4,%5,%6,%7}, {%8,%9}, {%0,%1,%2,%3};" \
        : "+f"((c)[0]), "+f"((c)[1]), "+f"((c)[2]), "+f"((c)[3]) \
        : "r"((a)[0]), "r"((a)[1]), "r"((a)[2]), "r"((a)[3]), "r"(b0), "r"(b1))

// pack f16x2 from two fp32 (lo -> low half, hi -> high half), round-nearest
#define PACK_F16X2_RN(d, lo, hi) \
    asm("cvt.rn.f16x2.f32 %0, %1, %2;" : "=r"(d) : "f"(hi), "f"(lo))

// ---------------------------------------------------------------------------
// rope table: one thread per (n, d<32)
// ---------------------------------------------------------------------------
__global__ void rtab_kernel(const float* __restrict__ rot)
{
    int i = blockIdx.x * blockDim.x + threadIdx.x;   // N_*32
    int n = i >> 5, d = i & 31;
    float p1 = rot[n * DH_ + d];
    float p2 = rot[n * DH_ + d + 32];
    g_rtab[i] = make_float4(cosf(p1), sinf(p1), cosf(p2), sinf(p2));
}

// ---------------------------------------------------------------------------
// x -> [Ah|Al] fp16 (2-term), stride KA_
// ---------------------------------------------------------------------------
__global__ void asplit_kernel(const float* __restrict__ src, __half* __restrict__ dst,
                              int total_quads)
{
    int i = blockIdx.x * blockDim.x + threadIdx.x;
    if (i >= total_quads) return;
    int r = i >> 8;
    int c = (i & 255) << 2;
    float4 v = ((const float4*)src)[i];
    __half h0 = __float2half_rn(v.x), h1 = __float2half_rn(v.y);
    __half h2 = __float2half_rn(v.z), h3 = __float2half_rn(v.w);
    __half l0 = __float2half_rn(v.x - __half2float(h0));
    __half l1 = __float2half_rn(v.y - __half2float(h1));
    __half l2 = __float2half_rn(v.z - __half2float(h2));
    __half l3 = __float2half_rn(v.w - __half2float(h3));
    size_t base = (size_t)r * KA_ + c;
    __half2* d0 = (__half2*)(dst + base);
    __half2* d1 = (__half2*)(dst + base + 1024);
    d0[0] = __halves2half2(h0, h1); d0[1] = __halves2half2(h2, h3);
    d1[0] = __halves2half2(l0, l1); d1[1] = __halves2half2(l2, l3);
}

// ---------------------------------------------------------------------------
// combined weight convert: w_qkv [3072,1024] + w_out [1024,1024] -> fp16
// ---------------------------------------------------------------------------
__global__ void wconv_kernel(const float* __restrict__ wq, const float* __restrict__ wo,
                             __half* __restrict__ dq, __half* __restrict__ dw)
{
    int i = blockIdx.x * blockDim.x + threadIdx.x;   // 4096*256 quads
    int r = i >> 8;
    int c = (i & 255) << 2;
    const float4 v = (r < 3072) ? ((const float4*)wq)[i]
                                : ((const float4*)wo)[(size_t)(r - 3072) * 256 + (i & 255)];
    __half2 a = __halves2half2(__float2half_rn(v.x), __float2half_rn(v.y));
    __half2 b = __halves2half2(__float2half_rn(v.z), __float2half_rn(v.w));
    __half* dst = (r < 3072) ? dq + (size_t)r * KB_ + c
                             : dw + (size_t)(r - 3072) * KB_ + c;
    ((__half2*)dst)[0] = a;
    ((__half2*)dst)[1] = b;
}

// ---------------------------------------------------------------------------
// QKV GEMM with fused RoPE epilogue.
// C = A([Ah|Al], K=2048) x B(w_qkv fp16, k wraps at 1024), CTA 128x128, BK=32.
// Warp tile 32x64 (4x2 warps): each thread holds both rope partners
// (d, d+32) of a head in acc[mi][ni] / acc[mi][ni+4] -> no exchange needed.
// Epilogue: region q -> rope*QSCALE -> g_qsh; k -> rope -> g_ksh; v -> g_vhh.
// ---------------------------------------------------------------------------
#define BK_ 32
#define ROWB_ 80
#define STAGE_ (128 * ROWB_ * 2)
#define GEMM_SMEM (4 * STAGE_)

__global__ __launch_bounds__(256, 2) void gemm_qkv(
    const __half* __restrict__ A, const __half* __restrict__ Bm)
{
    extern __shared__ char smem_raw[];
    const uint32_t sb = smem_to_u32(smem_raw);

    const int tid = threadIdx.x;
    const int lane = tid & 31, wid = tid >> 5;
    const int bm = blockIdx.y * 128, bn = blockIdx.x * 128;
    const int wm = (wid >> 1) * 32, wn = (wid & 1) * 64;

    const __half* Abase = A + (size_t)bm * KA_;
    const __half* Bbase = Bm + (size_t)bn * KB_;

    const int lrow = tid >> 1;
    const int lhalfB = (tid & 1) * 32;
    const int lhalfE = (tid & 1) * 16;
    const uint32_t so = (uint32_t)(lrow * ROWB_ + lhalfB);

    const uint32_t a_off = (uint32_t)((wm + (lane & 15)) * ROWB_ + (lane >> 4) * 16);
    const uint32_t b_off = (uint32_t)((wn + ((lane >> 4) << 3) + (lane & 7)) * ROWB_
                                      + ((lane >> 3) & 1) * 16);

    float acc[2][8][4];
#pragma unroll
    for (int mi = 0; mi < 2; mi++)
#pragma unroll
        for (int ni = 0; ni < 8; ni++)
#pragma unroll
            for (int r = 0; r < 4; r++) acc[mi][ni][r] = 0.f;

    auto load_tile = [&](int it) {
        uint32_t sa = sb + (uint32_t)(it & 3) * STAGE_;
        uint32_t sbb = sa + 128 * ROWB_;
        int kB = (it & 31) * BK_;          // B k wraps at 1024
        const __half* Ag = Abase + (size_t)lrow * KA_ + it * BK_ + lhalfE;
        const __half* Bg = Bbase + (size_t)lrow * KB_ + kB + lhalfE;
        cp_async16(sa + so, Ag);
        cp_async16(sa + so + 16, Ag + 8);
        cp_async16(sbb + so, Bg);
        cp_async16(sbb + so + 16, Bg + 8);
        CP_COMMIT();
    };

    load_tile(0);
    load_tile(1);
    load_tile(2);

    for (int it = 0; it < NITER_; it++) {
        CP_WAIT2();
        __syncthreads();
        if (it + 3 < NITER_) load_tile(it + 3);

        uint32_t sa = sb + (uint32_t)(it & 3) * STAGE_;
        uint32_t sbb = sa + 128 * ROWB_;
#pragma unroll
        for (int ks = 0; ks < 2; ks++) {
            uint32_t af[2][4], bf[4][4];
#pragma unroll
            for (int mi = 0; mi < 2; mi++)
                LDMATRIX_X4(af[mi], sa + a_off + mi * (16 * ROWB_) + ks * 32);
#pragma unroll
            for (int nb = 0; nb < 4; nb++)
                LDMATRIX_X4(bf[nb], sbb + b_off + nb * (16 * ROWB_) + ks * 32);
#pragma unroll
            for (int mi = 0; mi < 2; mi++)
#pragma unroll
                for (int ni = 0; ni < 8; ni++)
                    MMA16816H(acc[mi][ni], af[mi], bf[ni >> 1][(ni & 1) * 2],
                              bf[ni >> 1][(ni & 1) * 2 + 1]);
        }
    }

    // ---- fused RoPE epilogue ----
    const int region = bn >> 10;                 // 0=q, 1=k, 2=v
    const float scale = (region == 0) ? QSCALE_ : 1.0f;
    __half* dst = (region == 0) ? g_qsh : ((region == 1) ? g_ksh : g_vhh);

#pragma unroll
    for (int mi = 0; mi < 2; mi++) {
#pragma unroll
        for (int rh = 0; rh < 2; rh++) {
            int gr = bm + wm + mi * 16 + (lane >> 2) + rh * 8;   // global token row
            int n = gr & (N_ - 1);
            int bb = gr >> 11;
#pragma unroll
            for (int ni = 0; ni < 4; ni++) {
                int dloc = ni * 8 + (lane & 3) * 2;              // d in [0,30], even
                int gc = bn + wn + dloc;
                int h = (gc >> 6) & 15;
                size_t o = ((size_t)(bb * 16 + h) * N_ + n) * 64 + dloc;

                float v0 = acc[mi][ni][rh * 2],     v1 = acc[mi][ni][rh * 2 + 1];
                float w0 = acc[mi][ni + 4][rh * 2], w1 = acc[mi][ni + 4][rh * 2 + 1];

                float o0, o1, p0, p1;
                if (region < 2) {
                    float4 t0 = g_rtab[n * 32 + dloc];
                    float4 t1 = g_rtab[n * 32 + dloc + 1];
                    o0 = (v0 * t0.x - w0 * t0.y) * scale;
                    p0 = (w0 * t0.z + v0 * t0.w) * scale;
                    o1 = (v1 * t1.x - w1 * t1.y) * scale;
                    p1 = (w1 * t1.z + v1 * t1.w) * scale;
                } else {
                    o0 = v0; o1 = v1; p0 = w0; p1 = w1;
                }
                *(__half2*)(dst + o) =
                    __halves2half2(__float2half_rn(o0), __float2half_rn(o1));
                *(__half2*)(dst + o + 32) =
                    __halves2half2(__float2half_rn(p0), __float2half_rn(p1));
            }
        }
    }
}

// ---------------------------------------------------------------------------
// out-proj GEMM (unchanged structure): C = A([Ah|Al]) x B(w_out) + bias, fp32 out
// ---------------------------------------------------------------------------
__global__ __launch_bounds__(256, 2) void gemm_mma(
    const __half* __restrict__ A, const __half* __restrict__ Bm,
    float* __restrict__ C, const float* __restrict__ bias, int Ncol)
{
    extern __shared__ char smem_raw[];
    const uint32_t sb = smem_to_u32(smem_raw);

    const int tid = threadIdx.x;
    const int lane = tid & 31, wid = tid >> 5;
    const int bm = blockIdx.y * 128, bn = blockIdx.x * 128;
    const int wm = (wid >> 2) * 64, wn = (wid & 3) * 32;

    const __half* Abase = A + (size_t)bm * KA_;
    const __half* Bbase = Bm + (size_t)bn * KB_;

    const int lrow = tid >> 1;
    const int lhalfB = (tid & 1) * 32;
    const int lhalfE = (tid & 1) * 16;
    const uint32_t so = (uint32_t)(lrow * ROWB_ + lhalfB);

    const uint32_t a_off = (uint32_t)((wm + (lane & 15)) * ROWB_ + (lane >> 4) * 16);
    const uint32_t b_off = (uint32_t)((wn + ((lane >> 4) << 3) + (lane & 7)) * ROWB_
                                      + ((lane >> 3) & 1) * 16);

    float acc[4][4][4];
#pragma unroll
    for (int mi = 0; mi < 4; mi++)
#pragma unroll
        for (int ni = 0; ni < 4; ni++)
#pragma unroll
            for (int r = 0; r < 4; r++) acc[mi][ni][r] = 0.f;

    auto load_tile = [&](int it) {
        uint32_t sa = sb + (uint32_t)(it & 3) * STAGE_;
        uint32_t sbb = sa + 128 * ROWB_;
        int kB = (it & 31) * BK_;
        const __half* Ag = Abase + (size_t)lrow * KA_ + it * BK_ + lhalfE;
        const __half* Bg = Bbase + (size_t)lrow * KB_ + kB + lhalfE;
        cp_async16(sa + so, Ag);
        cp_async16(sa + so + 16, Ag + 8);
        cp_async16(sbb + so, Bg);
        cp_async16(sbb + so + 16, Bg + 8);
        CP_COMMIT();
    };

    load_tile(0);
    load_tile(1);
    load_tile(2);

    for (int it = 0; it < NITER_; it++) {
        CP_WAIT2();
        __syncthreads();
        if (it + 3 < NITER_) load_tile(it + 3);

        uint32_t sa = sb + (uint32_t)(it & 3) * STAGE_;
        uint32_t sbb = sa + 128 * ROWB_;
#pragma unroll
        for (int ks = 0; ks < 2; ks++) {
            uint32_t af[4][4], bf[2][4];
#pragma unroll
            for (int mi = 0; mi < 4; mi++)
                LDMATRIX_X4(af[mi], sa + a_off + mi * (16 * ROWB_) + ks * 32);
#pragma unroll
            for (int nb = 0; nb < 2; nb++)
                LDMATRIX_X4(bf[nb], sbb + b_off + nb * (16 * ROWB_) + ks * 32);
#pragma unroll
            for (int mi = 0; mi < 4; mi++)
#pragma unroll
                for (int ni = 0; ni < 4; ni++)
                    MMA16816H(acc[mi][ni], af[mi], bf[ni >> 1][(ni & 1) * 2],
                              bf[ni >> 1][(ni & 1) * 2 + 1]);
        }
    }

#pragma unroll
    for (int mi = 0; mi < 4; mi++) {
        int row = bm + wm + mi * 16 + (lane >> 2);
#pragma unroll
        for (int ni = 0; ni < 4; ni++) {
            int col = bn + wn + ni * 8 + (lane & 3) * 2;
            float b0 = bias[col], b1 = bias[col + 1];
            float2 v0 = make_float2(acc[mi][ni][0] + b0, acc[mi][ni][1] + b1);
            float2 v1 = make_float2(acc[mi][ni][2] + b0, acc[mi][ni][3] + b1);
            *(float2*)(C + (size_t)row * Ncol + col) = v0;
            *(float2*)(C + (size_t)(row + 8) * Ncol + col) = v1;
        }
    }
}

// ---------------------------------------------------------------------------
// Tensor-core flash attention (fp16), fused [Ah|Al] epilogue into g_ax.
// ---------------------------------------------------------------------------
#define KT_ 64
#define NT_ (N_ / KT_)
#define KROWB_ 144
#define VROWB_ 144
#define AST_BYTES (2 * KT_ * 144)
#define ATTN_SMEM (2 * AST_BYTES)

__global__ __launch_bounds__(256, 2) void attn_mma()
{
    extern __shared__ char smem_raw[];
    const uint32_t sb = smem_to_u32(smem_raw);

    const int tid = threadIdx.x;
    const int lane = tid & 31, wid = tid >> 5;
    const int qt = blockIdx.x;
    const int bh = blockIdx.y;
    const int b = bh >> 4, h = bh & 15;

    const __half* Kg = g_ksh + (size_t)bh * N_ * 64;
    const __half* Vg = g_vhh + (size_t)bh * N_ * 64;

    auto load_tile = [&](int t) {
        uint32_t st = sb + (uint32_t)(t & 1) * AST_BYTES;
        uint32_t v_st = st + KT_ * KROWB_;
        int kb = t * KT_;
#pragma unroll
        for (int j = 0; j < 2; j++) {
            int idx = tid + j * 256;
            int row = idx >> 3, c = idx & 7;
            cp_async16(st + row * KROWB_ + c * 16, Kg + (size_t)(kb + row) * 64 + c * 8);
            cp_async16(v_st + row * VROWB_ + c * 16, Vg + (size_t)(kb + row) * 64 + c * 8);
        }
        CP_COMMIT();
    };

    load_tile(0);

    // Q fragments via direct LDG in mma A-frag layout
    uint32_t af[4][4];
    {
        const __half* q0 = g_qsh
            + ((size_t)bh * N_ + qt * 128 + wid * 16 + (lane >> 2)) * 64 + (lane & 3) * 2;
        const __half* q8 = q0 + 8 * 64;
#pragma unroll
        for (int ks = 0; ks < 4; ks++) {
            af[ks][0] = *(const uint32_t*)(q0 + ks * 16);
            af[ks][1] = *(const uint32_t*)(q8 + ks * 16);
            af[ks][2] = *(const uint32_t*)(q0 + ks * 16 + 8);
            af[ks][3] = *(const uint32_t*)(q8 + ks * 16 + 8);
        }
    }

    float O[8][4];
#pragma unroll
    for (int g = 0; g < 8; g++)
#pragma unroll
        for (int r = 0; r < 4; r++) O[g][r] = 0.f;
    float m0 = -1e30f, m1 = -1e30f, l0 = 0.f, l1 = 0.f;

    const uint32_t kb_off = (uint32_t)((((lane >> 4) << 3) + (lane & 7)) * KROWB_
                                       + ((lane >> 3) & 1) * 16);
    const uint32_t v_off = (uint32_t)((((lane >> 3) & 1) * 8 + (lane & 7)) * VROWB_
                                      + ((lane >> 4) << 3) * 2);

    for (int t = 0; t < NT_; t++) {
        if (t + 1 < NT_) { load_tile(t + 1); CP_WAIT1(); } else { CP_WAIT0(); }
        __syncthreads();

        uint32_t st = sb + (uint32_t)(t & 1) * AST_BYTES;
        uint32_t v_st = st + KT_ * KROWB_;

        float S[8][4];
#pragma unroll
        for (int g = 0; g < 8; g++)
#pragma unroll
            for (int r = 0; r < 4; r++) S[g][r] = 0.f;

#pragma unroll
        for (int ks = 0; ks < 4; ks++) {
            uint32_t kf[4][4];
#pragma unroll
            for (int g = 0; g < 4; g++)
                LDMATRIX_X4(kf[g], st + kb_off + g * (16 * KROWB_) + ks * 32);
#pragma unroll
            for (int g = 0; g < 4; g++) {
                MMA16816H(S[2 * g],     af[ks], kf[g][0], kf[g][1]);
                MMA16816H(S[2 * g + 1], af[ks], kf[g][2], kf[g][3]);
            }
        }

        float mx0 = -1e30f, mx1 = -1e30f;
#pragma unroll
        for (int g = 0; g < 8; g++) {
            mx0 = fmaxf(mx0, fmaxf(S[g][0], S[g][1]));
            mx1 = fmaxf(mx1, fmaxf(S[g][2], S[g][3]));
        }
        mx0 = fmaxf(mx0, __shfl_xor_sync(0xffffffffu, mx0, 1));
        mx0 = fmaxf(mx0, __shfl_xor_sync(0xffffffffu, mx0, 2));
        mx1 = fmaxf(mx1, __shfl_xor_sync(0xffffffffu, mx1, 1));
        mx1 = fmaxf(mx1, __shfl_xor_sync(0xffffffffu, mx1, 2));

        float m0n = fmaxf(m0, mx0), m1n = fmaxf(m1, mx1);
        float corr0 = exp2f(m0 - m0n), corr1 = exp2f(m1 - m1n);
        m0 = m0n; m1 = m1n;
        l0 *= corr0; l1 *= corr1;

#pragma unroll
        for (int g = 0; g < 8; g++) {
            S[g][0] = exp2f(S[g][0] - m0);
            S[g][1] = exp2f(S[g][1] - m0);
            S[g][2] = exp2f(S[g][2] - m1);
            S[g][3] = exp2f(S[g][3] - m1);
            l0 += S[g][0] + S[g][1];
            l1 += S[g][2] + S[g][3];
            O[g][0] *= corr0; O[g][1] *= corr0;
            O[g][2] *= corr1; O[g][3] *= corr1;
        }

#pragma unroll
        for (int ks = 0; ks < 4; ks++) {
            uint32_t ph[4];
            PACK_F16X2_RN(ph[0], S[2 * ks][0],     S[2 * ks][1]);
            PACK_F16X2_RN(ph[1], S[2 * ks][2],     S[2 * ks][3]);
            PACK_F16X2_RN(ph[2], S[2 * ks + 1][0], S[2 * ks + 1][1]);
            PACK_F16X2_RN(ph[3], S[2 * ks + 1][2], S[2 * ks + 1][3]);
#pragma unroll
            for (int g = 0; g < 4; g++) {
                uint32_t vf[4];
                LDMATRIX_X4_T(vf, v_st + v_off + ks * (16 * VROWB_) + g * 32);
                MMA16816H(O[2 * g],     ph, vf[0], vf[1]);
                MMA16816H(O[2 * g + 1], ph, vf[2], vf[3]);
            }
        }
        __syncthreads();
    }

    // ---- finalize: fused 2-term fp16 split into g_ax ----
    l0 += __shfl_xor_sync(0xffffffffu, l0, 1);
    l0 += __shfl_xor_sync(0xffffffffu, l0, 2);
    l1 += __shfl_xor_sync(0xffffffffu, l1, 1);
    l1 += __shfl_xor_sync(0xffffffffu, l1, 2);
    float inv0 = 1.f / l0, inv1 = 1.f / l1;

    int row = qt * 128 + wid * 16 + (lane >> 2);
    size_t base = ((size_t)(b * N_ + row)) * KA_ + h * 64 + (lane & 3) * 2;
#pragma unroll
    for (int g = 0; g < 8; g++) {
        float a0 = O[g][0] * inv0, a1 = O[g][1] * inv0;
        float c0 = O[g][2] * inv1, c1 = O[g][3] * inv1;
        __half ha0 = __float2half_rn(a0), ha1 = __float2half_rn(a1);
        __half hc0 = __float2half_rn(c0), hc1 = __float2half_rn(c1);
        __half la0 = __float2half_rn(a0 - __half2float(ha0));
        __half la1 = __float2half_rn(a1 - __half2float(ha1));
        __half lc0 = __float2half_rn(c0 - __half2float(hc0));
        __half lc1 = __float2half_rn(c1 - __half2float(hc1));
        *(__half2*)(g_ax + base + g * 8)                        = __halves2half2(ha0, ha1);
        *(__half2*)(g_ax + base + 1024 + g * 8)                 = __halves2half2(la0, la1);
        *(__half2*)(g_ax + base + 8 * (size_t)KA_ + g * 8)          = __halves2half2(hc0, hc1);
        *(__half2*)(g_ax + base + 8 * (size_t)KA_ + 1024 + g * 8)   = __halves2half2(lc0, lc1);
    }
}

// ---------------------------------------------------------------------------
extern "C" void kernel_launch(void* const* d_in, const int* in_sizes, int n_in,
                              void* d_out, int out_size)
{
    (void)in_sizes; (void)n_in; (void)out_size;
    const float* x     = (const float*)d_in[0];
    const float* rot   = (const float*)d_in[1];
    const float* w_qkv = (const float*)d_in[2];
    const float* w_out = (const float*)d_in[3];
    const float* b_out = (const float*)d_in[4];
    float* out = (float*)d_out;

    __half *p_ax, *p_bq, *p_bo;
    cudaGetSymbolAddress((void**)&p_ax, g_ax);
    cudaGetSymbolAddress((void**)&p_bq, g_bq);
    cudaGetSymbolAddress((void**)&p_bo, g_bo);

    cudaFuncSetAttribute(gemm_qkv, cudaFuncAttributeMaxDynamicSharedMemorySize, GEMM_SMEM);
    cudaFuncSetAttribute(gemm_mma, cudaFuncAttributeMaxDynamicSharedMemorySize, GEMM_SMEM);
    cudaFuncSetAttribute(attn_mma, cudaFuncAttributeMaxDynamicSharedMemorySize, ATTN_SMEM);

    // 1) rope cos/sin table + operand conversions
    rtab_kernel<<<(N_ * 32) / 256, 256>>>(rot);
    asplit_kernel<<<(4096 * 256) / 256, 256>>>(x, p_ax, 4096 * 256);
    wconv_kernel<<<(4096 * 256) / 256, 256>>>(w_qkv, w_out, p_bq, p_bo);

    // 2) QKV projection + fused RoPE -> g_qsh/g_ksh/g_vhh (fp16)
    {
        dim3 grid(3072 / 128, 4096 / 128);
        gemm_qkv<<<grid, 256, GEMM_SMEM>>>(p_ax, p_bq);
    }

    // 3) Attention + fused [Ah|Al] split -> g_ax
    {
        dim3 grid(N_ / 128, 32);
        attn_mma<<<grid, 256, ATTN_SMEM>>>();
    }

    // 4) Output projection + bias
    {
        dim3 grid(1024 / 128, 4096 / 128);
        gemm_mma<<<grid, 256, GEMM_SMEM>>>(p_ax, p_bo, out, b_out, 1024);
    }
}